// round 12
// baseline (speedup 1.0000x reference)
#include <cuda_runtime.h>
#include <cuda_fp16.h>
#include <math.h>
#include <stdint.h>

#define T_TOK 8192
#define DIM   768
#define FF    3072
#define NE    8
#define CAP   2560
#define MAXR  5120   // 2*CAP, max gathered rows per expert

// ---------------- static device scratch ----------------
__device__ __half g_Wg_h[(size_t)NE * FF * DIM];
__device__ __half g_Wu_h[(size_t)NE * FF * DIM];
__device__ __half g_Wo_h[(size_t)NE * DIM * FF];
__device__ __half g_X_h[(size_t)T_TOK * DIM];
__device__ __half g_H_h[(size_t)NE * MAXR * FF];
__device__ int    g_tok[NE * MAXR];
__device__ float  g_wrow[NE * MAXR];   // combine weight per gathered row
__device__ int    g_topk[T_TOK * 2];
__device__ float  g_topp[T_TOK * 2];
__device__ int    g_cnt[NE];
__device__ int    g_cnta[NE];
__device__ float  g_psum[NE];
__device__ float  g_zsum;

// ---------------- helpers ----------------
__device__ __forceinline__ uint32_t su32(const void* p) {
    uint32_t a;
    asm("{ .reg .u64 t; cvta.to.shared.u64 t, %1; cvt.u32.u64 %0, t; }" : "=r"(a) : "l"(p));
    return a;
}
__device__ __forceinline__ void cp16(uint32_t dst, const void* src) {
    asm volatile("cp.async.cg.shared.global [%0], [%1], 16;" :: "r"(dst), "l"(src) : "memory");
}
#define CP_COMMIT() asm volatile("cp.async.commit_group;" ::: "memory")
#define CP_WAIT_2() asm volatile("cp.async.wait_group 2;" ::: "memory")

// split block barrier: each thread contributes 1 arrive + 1 sync -> count 512 for 256 threads
#define BAR_ARRIVE_ID(id) asm volatile("bar.arrive %0, 512;" :: "r"(id) : "memory")
#define BAR_SYNC_ID(id)   asm volatile("bar.sync %0, 512;"   :: "r"(id) : "memory")

#define MMA_F16(D, A, B0, B1)                                                    \
    asm volatile(                                                                \
        "mma.sync.aligned.m16n8k16.row.col.f32.f16.f16.f32 "                     \
        "{%0,%1,%2,%3}, {%4,%5,%6,%7}, {%8,%9}, {%0,%1,%2,%3};\n"                \
        : "+f"((D)[0]), "+f"((D)[1]), "+f"((D)[2]), "+f"((D)[3])                 \
        : "r"((A)[0]), "r"((A)[1]), "r"((A)[2]), "r"((A)[3]), "r"(B0), "r"(B1))

#define LDSM4(R, addr)                                                           \
    asm volatile("ldmatrix.sync.aligned.m8n8.x4.shared.b16 {%0,%1,%2,%3}, [%4];" \
        : "=r"((R)[0]), "=r"((R)[1]), "=r"((R)[2]), "=r"((R)[3]) : "r"(addr))

// ---------------- fused prep: aux-zero + out-zero + fp32->fp16 cvt ----------------
#define NX8 ((T_TOK * DIM) / 8)          // 786432 packs (16B fp16 each)
#define NW8 ((NE * FF * DIM) / 8)        // 2359296
#define CVT_TOT (NX8 + 3 * NW8)          // 7864320 packs
#define CVT_HALF (CVT_TOT / 2)           // 3932160 threads, 2 packs each
#define ZERO_THREADS ((T_TOK * DIM) / 8) // 786432 threads, 2 float4 each
#define PREP_THREADS (CVT_HALF + ZERO_THREADS)

__device__ __forceinline__ uint4 cvt_pack(float4 v0, float4 v1) {
    __half2 h0 = __floats2half2_rn(v0.x, v0.y);
    __half2 h1 = __floats2half2_rn(v0.z, v0.w);
    __half2 h2 = __floats2half2_rn(v1.x, v1.y);
    __half2 h3 = __floats2half2_rn(v1.z, v1.w);
    uint4 o;
    o.x = *(const uint32_t*)&h0; o.y = *(const uint32_t*)&h1;
    o.z = *(const uint32_t*)&h2; o.w = *(const uint32_t*)&h3;
    return o;
}

__global__ void prep_kernel(const float* __restrict__ x,  const float* __restrict__ wig,
                            const float* __restrict__ wiu, const float* __restrict__ wo,
                            float* __restrict__ out) {
    int i = blockIdx.x * blockDim.x + threadIdx.x;
    if (i < CVT_HALF) {
        int j = 2 * i;
        const float* s;
        __half* d;
        int k;
        if (j < NX8)                { s = x;   d = g_X_h;  k = j; }
        else if (j < NX8 + NW8)     { s = wig; d = g_Wg_h; k = j - NX8; }
        else if (j < NX8 + 2 * NW8) { s = wiu; d = g_Wu_h; k = j - NX8 - NW8; }
        else                        { s = wo;  d = g_Wo_h; k = j - NX8 - 2 * NW8; }
        float4 v0 = ((const float4*)s)[2 * k];
        float4 v1 = ((const float4*)s)[2 * k + 1];
        float4 v2 = ((const float4*)s)[2 * k + 2];
        float4 v3 = ((const float4*)s)[2 * k + 3];
        ((uint4*)d)[k]     = cvt_pack(v0, v1);
        ((uint4*)d)[k + 1] = cvt_pack(v2, v3);
    } else if (i < PREP_THREADS) {
        int z = i - CVT_HALF;
        float4 zz = make_float4(0.f, 0.f, 0.f, 0.f);
        ((float4*)out)[2 * z]     = zz;
        ((float4*)out)[2 * z + 1] = zz;
        if (z == 0) {
#pragma unroll
            for (int e = 0; e < NE; e++) { g_psum[e] = 0.f; g_cnta[e] = 0; }
            g_zsum = 0.f;
        }
    }
}

// ---------------- router: 512 threads (16 tokens/block) ----------------
__global__ void router_kernel(const float* __restrict__ x, const float* __restrict__ wg) {
    __shared__ float sg[NE * DIM];
    __shared__ float shp[NE];
    __shared__ int   shc[NE];
    __shared__ float shz;
    int tid = threadIdx.x;
    for (int i = tid; i < NE * DIM; i += 512) sg[i] = wg[i];
    if (tid < NE) { shp[tid] = 0.f; shc[tid] = 0; }
    if (tid == 0) shz = 0.f;
    __syncthreads();

    int w = tid >> 5, lane = tid & 31;
    int t = blockIdx.x * 16 + w;
    const float* xt = x + (size_t)t * DIM;
    float acc[NE];
#pragma unroll
    for (int e = 0; e < NE; e++) acc[e] = 0.f;
    for (int j = lane; j < DIM; j += 32) {
        float xv = xt[j];
#pragma unroll
        for (int e = 0; e < NE; e++) acc[e] += xv * sg[e * DIM + j];
    }
#pragma unroll
    for (int o = 16; o > 0; o >>= 1) {
#pragma unroll
        for (int e = 0; e < NE; e++) acc[e] += __shfl_xor_sync(0xffffffffu, acc[e], o);
    }
    if (lane == 0) {
        float m = acc[0];
#pragma unroll
        for (int e = 1; e < NE; e++) m = fmaxf(m, acc[e]);
        float p[NE]; float s = 0.f;
#pragma unroll
        for (int e = 0; e < NE; e++) { p[e] = expf(acc[e] - m); s += p[e]; }
        float inv = 1.f / s;
#pragma unroll
        for (int e = 0; e < NE; e++) p[e] *= inv;
        float lse = m + logf(s);
        int i0 = 0; float b0 = p[0];
#pragma unroll
        for (int e = 1; e < NE; e++) if (p[e] > b0) { b0 = p[e]; i0 = e; }
        int i1 = -1; float b1 = -1.f;
#pragma unroll
        for (int e = 0; e < NE; e++) if (e != i0 && p[e] > b1) { b1 = p[e]; i1 = e; }
        float invs = 1.f / (b0 + b1);
        g_topk[t * 2] = i0; g_topk[t * 2 + 1] = i1;
        g_topp[t * 2] = b0 * invs; g_topp[t * 2 + 1] = b1 * invs;
#pragma unroll
        for (int e = 0; e < NE; e++) atomicAdd(&shp[e], p[e]);
        atomicAdd(&shc[i0], 1);
        atomicAdd(&shc[i1], 1);
        atomicAdd(&shz, lse * lse);
    }
    __syncthreads();
    if (tid < NE) { atomicAdd(&g_psum[tid], shp[tid]); atomicAdd(&g_cnta[tid], shc[tid]); }
    if (tid == 0) atomicAdd(&g_zsum, shz);
}

// ---------------- scan: 1024 threads, 8 stripes ----------------
__global__ void scan_kernel() {
    int e = blockIdx.x;
    int tid = threadIdx.x;
    int w = tid >> 5, lane = tid & 31;
    unsigned ltm = (1u << lane) - 1u;
    __shared__ int sw0[32], sw1[32], sws[32];
    __shared__ int base0, base1, baseS;
    if (tid == 0) { base0 = 0; base1 = 0; baseS = 0; }
    __syncthreads();
    for (int b = 0; b < T_TOK; b += 1024) {
        int t = b + tid;
        int i0 = g_topk[t * 2], i1 = g_topk[t * 2 + 1];
        int a0 = (i0 == e) ? 1 : 0;
        int a1 = (i1 == e) ? 1 : 0;
        unsigned m0b = __ballot_sync(0xffffffffu, a0);
        unsigned m1b = __ballot_sync(0xffffffffu, a1);
        if (lane == 0) { sw0[w] = __popc(m0b); sw1[w] = __popc(m1b); }
        __syncthreads();
        int off0 = base0, off1 = base1;
        for (int j = 0; j < w; j++) { off0 += sw0[j]; off1 += sw1[j]; }
        int r0 = off0 + __popc(m0b & ltm);
        int r1 = off1 + __popc(m1b & ltm);
        int k0 = a0 && (r0 < CAP);
        int k1 = a1 && (r1 < CAP);
        int sel = (k0 || k1) ? 1 : 0;
        unsigned msb = __ballot_sync(0xffffffffu, sel);
        if (lane == 0) sws[w] = __popc(msb);
        __syncthreads();
        int offS = baseS;
        for (int j = 0; j < w; j++) offS += sws[j];
        int pos = offS + __popc(msb & ltm);
        if (sel) {
            g_tok[e * MAXR + pos] = t;
            g_wrow[e * MAXR + pos] = k0 ? g_topp[t * 2] : g_topp[t * 2 + 1];
        }
        __syncthreads();
        if (tid == 0) {
            int t0 = 0, t1 = 0, ts = 0;
            for (int j = 0; j < 32; j++) { t0 += sw0[j]; t1 += sw1[j]; ts += sws[j]; }
            base0 += t0; base1 += t1; baseS += ts;
        }
        __syncthreads();
    }
    if (tid == 0) g_cnt[e] = baseS;
}

// ---------------- GEMM config (round-10 proven best + split barriers) ----------------
#define BM 128
#define BK 32                  // halves per k-tile (2 x k16 mma steps)
#define LDH 40                 // halves per smem row (32 data + 8 pad), LDSM-conflict-free
#define G1_STAGE 20480u        // bytes: A(128x40x2=10240) + G(64x40x2=5120) + U(5120)
#define G1_GOFF  10240u
#define G1_UOFF  15360u
#define G2_STAGE 20480u        // bytes: A(10240) + B(128x40x2=10240)
#define G2_BOFF  10240u
#define NSTAGE 4

// GEMM1: H = silu(Xg @ Wg^T) * (Xg @ Wu^T); BM=128, BN=64 (per matrix)
// warps 4(m) x 2(n), warp tile 32x32, LDSM fragments, 2 CTAs/SM
// split arrive/wait barriers: MMA tail of iter kt overlaps LDSMs of iter kt+1
__global__ __launch_bounds__(256, 2) void gemm1_kernel() {
    int e = blockIdx.z;
    int cnt = g_cnt[e];
    int m0 = blockIdx.y * BM;
    if (m0 >= cnt) return;
    int n0 = blockIdx.x * 64;

    extern __shared__ __half sm[];
    __shared__ int stok[BM];
    int tid = threadIdx.x;
    if (tid < BM) { int r = m0 + tid; stok[tid] = (r < cnt) ? g_tok[e * MAXR + r] : 0; }
    __syncthreads();

    uint32_t sb = su32(sm);
    int rr = tid >> 1;
    int ko = (tid & 1) * 16;
    const __half* srcA = g_X_h + (size_t)stok[rr] * DIM + ko;
    uint32_t dstA = sb + (uint32_t)(rr * LDH + ko) * 2;
    int bro = (tid & 127) >> 1;   // 0..63
    const __half* srcB = ((tid < 128) ? g_Wg_h : g_Wu_h) + ((size_t)e * FF + n0 + bro) * DIM + ko;
    uint32_t dstB = sb + ((tid < 128) ? G1_GOFF : G1_UOFF) + (uint32_t)(bro * LDH + ko) * 2;

#define G1_ISSUE(s, kt) do {                                           \
        uint32_t b_ = (uint32_t)(s) * G1_STAGE;                        \
        int kh_ = (kt) * BK;                                           \
        cp16(dstA + b_, srcA + kh_); cp16(dstA + b_ + 16, srcA + kh_ + 8); \
        cp16(dstB + b_, srcB + kh_); cp16(dstB + b_ + 16, srcB + kh_ + 8); \
    } while (0)

    int lane = tid & 31, wid = tid >> 5;
    int g = lane >> 2, t4 = lane & 3;
    int wm = wid & 3, wn = wid >> 2;   // 4 x 2 warp grid

    uint32_t offA[2], offB[2];
#pragma unroll
    for (int im = 0; im < 2; im++)
        offA[im] = (uint32_t)((wm * 32 + im * 16 + (lane & 15)) * LDH + (lane >> 4) * 8) * 2;
#pragma unroll
    for (int p = 0; p < 2; p++)
        offB[p] = G1_GOFF + (uint32_t)((wn * 32 + (p * 2 + (lane >> 4)) * 8 + (lane & 7)) * LDH
                                       + ((lane >> 3) & 1) * 8) * 2;

    float ag[2][4][4], au[2][4][4];
#pragma unroll
    for (int i = 0; i < 2; i++)
#pragma unroll
        for (int j = 0; j < 4; j++)
#pragma unroll
            for (int c = 0; c < 4; c++) { ag[i][j][c] = 0.f; au[i][j][c] = 0.f; }

    G1_ISSUE(0, 0); CP_COMMIT();
    G1_ISSUE(1, 1); CP_COMMIT();
    G1_ISSUE(2, 2); CP_COMMIT();
    BAR_ARRIVE_ID(1);   // prime barrier 1 for iter 0's sync

    const int NK = DIM / BK;  // 24
    for (int kt = 0; kt < NK; kt++) {
        CP_WAIT_2();
        BAR_SYNC_ID(1 + (kt & 1));   // all cp-waits done AND all prior-iter LDSM reads done
        if (kt + 3 < NK) G1_ISSUE((kt + 3) % NSTAGE, kt + 3);
        CP_COMMIT();
        uint32_t stb = sb + (uint32_t)(kt % NSTAGE) * G1_STAGE;
#pragma unroll
        for (int km = 0; km < 2; km++) {
            uint32_t kmo = km * 32;
            uint32_t a[2][4], gq[2][4], uq[2][4];
            LDSM4(a[0], stb + offA[0] + kmo);
            LDSM4(a[1], stb + offA[1] + kmo);
            LDSM4(gq[0], stb + offB[0] + kmo);
            LDSM4(gq[1], stb + offB[1] + kmo);
            LDSM4(uq[0], stb + offB[0] + (G1_UOFF - G1_GOFF) + kmo);
            LDSM4(uq[1], stb + offB[1] + (G1_UOFF - G1_GOFF) + kmo);
            if (km == 1) BAR_ARRIVE_ID(2 - (kt & 1));   // my smem reads for this iter done
#pragma unroll
            for (int p = 0; p < 2; p++) {
#pragma unroll
                for (int s = 0; s < 2; s++) {
                    int jn = p * 2 + s;
#pragma unroll
                    for (int im = 0; im < 2; im++) {
                        MMA_F16(ag[im][jn], a[im], gq[p][s * 2], gq[p][s * 2 + 1]);
                        MMA_F16(au[im][jn], a[im], uq[p][s * 2], uq[p][s * 2 + 1]);
                    }
                }
            }
        }
    }

    // epilogue: h = silu(g) * u, store fp16 H
#pragma unroll
    for (int im = 0; im < 2; im++) {
#pragma unroll
        for (int jn = 0; jn < 4; jn++) {
            int rl  = wm * 32 + im * 16 + g;
            int col = n0 + wn * 32 + jn * 8 + t4 * 2;
            size_t b0i = (size_t)(e * MAXR + m0 + rl) * FF + col;
            size_t b1i = (size_t)(e * MAXR + m0 + rl + 8) * FF + col;
            float gg, uu, h0x, h0y, h1x, h1y;
            gg = ag[im][jn][0]; uu = au[im][jn][0]; h0x = gg / (1.f + expf(-gg)) * uu;
            gg = ag[im][jn][1]; uu = au[im][jn][1]; h0y = gg / (1.f + expf(-gg)) * uu;
            gg = ag[im][jn][2]; uu = au[im][jn][2]; h1x = gg / (1.f + expf(-gg)) * uu;
            gg = ag[im][jn][3]; uu = au[im][jn][3]; h1y = gg / (1.f + expf(-gg)) * uu;
            *(__half2*)&g_H_h[b0i] = __floats2half2_rn(h0x, h0y);
            *(__half2*)&g_H_h[b1i] = __floats2half2_rn(h1x, h1y);
        }
    }
}

// GEMM2 + fused combine: out[tok] += w * (H @ Wo^T); BM=128, BN=128, warps 4x2, 2 CTAs/SM
__global__ __launch_bounds__(256, 2) void gemm2_kernel(float* __restrict__ out) {
    int e = blockIdx.z;
    int cnt = g_cnt[e];
    int m0 = blockIdx.y * BM;
    if (m0 >= cnt) return;
    int n0 = blockIdx.x * 128;

    extern __shared__ __half sm[];
    __shared__ int   stok[BM];
    __shared__ float swt[BM];
    int tid = threadIdx.x;
    if (tid < BM) {
        int r = m0 + tid;
        bool v = r < cnt;
        stok[tid] = v ? g_tok[e * MAXR + r] : 0;
        swt[tid]  = v ? g_wrow[e * MAXR + r] : 0.f;
    }

    uint32_t sb = su32(sm);
    int rr = tid >> 1;
    int ko = (tid & 1) * 16;
    const __half* srcA = g_H_h + (size_t)(e * MAXR + m0 + rr) * FF + ko;
    uint32_t dstA = sb + (uint32_t)(rr * LDH + ko) * 2;
    const __half* srcB = g_Wo_h + ((size_t)e * DIM + n0 + rr) * FF + ko;
    uint32_t dstB = sb + G2_BOFF + (uint32_t)(rr * LDH + ko) * 2;

#define G2_ISSUE(s, kt) do {                                           \
        uint32_t b_ = (uint32_t)(s) * G2_STAGE;                        \
        int kh_ = (kt) * BK;                                           \
        cp16(dstA + b_, srcA + kh_); cp16(dstA + b_ + 16, srcA + kh_ + 8); \
        cp16(dstB + b_, srcB + kh_); cp16(dstB + b_ + 16, srcB + kh_ + 8); \
    } while (0)

    int lane = tid & 31, wid = tid >> 5;
    int g = lane >> 2, t4 = lane & 3;
    int wm = wid & 3, wn = wid >> 2;

    uint32_t offA[2], offB[4];
#pragma unroll
    for (int im = 0; im < 2; im++)
        offA[im] = (uint32_t)((wm * 32 + im * 16 + (lane & 15)) * LDH + (lane >> 4) * 8) * 2;
#pragma unroll
    for (int p = 0; p < 4; p++)
        offB[p] = G2_BOFF + (uint32_t)((wn * 64 + (p * 2 + (lane >> 4)) * 8 + (lane & 7)) * LDH
                                       + ((lane >> 3) & 1) * 8) * 2;

    float acc[2][8][4];
#pragma unroll
    for (int i = 0; i < 2; i++)
#pragma unroll
        for (int j = 0; j < 8; j++)
#pragma unroll
            for (int c = 0; c < 4; c++) acc[i][j][c] = 0.f;

    G2_ISSUE(0, 0); CP_COMMIT();
    G2_ISSUE(1, 1); CP_COMMIT();
    G2_ISSUE(2, 2); CP_COMMIT();
    // stok/swt written above are read only in the epilogue; barrier 1 prime also orders them
    BAR_ARRIVE_ID(1);

    const int NK = FF / BK;  // 96
    for (int kt = 0; kt < NK; kt++) {
        CP_WAIT_2();
        BAR_SYNC_ID(1 + (kt & 1));
        if (kt + 3 < NK) G2_ISSUE((kt + 3) % NSTAGE, kt + 3);
        CP_COMMIT();
        uint32_t stb = sb + (uint32_t)(kt % NSTAGE) * G2_STAGE;
#pragma unroll
        for (int km = 0; km < 2; km++) {
            uint32_t kmo = km * 32;
            uint32_t a[2][4], bq[4][4];
            LDSM4(a[0], stb + offA[0] + kmo);
            LDSM4(a[1], stb + offA[1] + kmo);
#pragma unroll
            for (int p = 0; p < 4; p++) LDSM4(bq[p], stb + offB[p] + kmo);
            if (km == 1) BAR_ARRIVE_ID(2 - (kt & 1));
#pragma unroll
            for (int p = 0; p < 4; p++) {
#pragma unroll
                for (int s = 0; s < 2; s++) {
                    int jn = p * 2 + s;
#pragma unroll
                    for (int im = 0; im < 2; im++)
                        MMA_F16(acc[im][jn], a[im], bq[p][s * 2], bq[p][s * 2 + 1]);
                }
            }
        }
    }
    __syncthreads();   // stok/swt visibility for epilogue (cheap, once)

    // fused combine epilogue: out[tok, col] += w * acc  (<=2 commutative contributions
    // per element -> order-independent -> deterministic)
#pragma unroll
    for (int im = 0; im < 2; im++) {
        int rl0 = wm * 32 + im * 16 + g;
        int rl1 = rl0 + 8;
        int tok0 = stok[rl0]; float w0 = swt[rl0];
        int tok1 = stok[rl1]; float w1 = swt[rl1];
        float* o0 = out + (size_t)tok0 * DIM;
        float* o1 = out + (size_t)tok1 * DIM;
#pragma unroll
        for (int jn = 0; jn < 8; jn++) {
            int col = n0 + wn * 64 + jn * 8 + t4 * 2;
            if (w0 > 0.f) {
                atomicAdd(o0 + col,     w0 * acc[im][jn][0]);
                atomicAdd(o0 + col + 1, w0 * acc[im][jn][1]);
            }
            if (w1 > 0.f) {
                atomicAdd(o1 + col,     w1 * acc[im][jn][2]);
                atomicAdd(o1 + col + 1, w1 * acc[im][jn][3]);
            }
        }
    }
}

// ---------------- finalize ----------------
__global__ void finalize_kernel(float* __restrict__ out, int out_size) {
    if (threadIdx.x == 0 && out_size > T_TOK * DIM) {
        float lb = 0.f;
        for (int e = 0; e < NE; e++) {
            float f = (float)g_cnta[e] / (float)(T_TOK * 2);
            float P = g_psum[e] / (float)T_TOK;
            lb += f * P;
        }
        lb *= (float)NE;
        float z = g_zsum / (float)T_TOK;
        out[T_TOK * DIM] = 0.01f * lb + 0.001f * z;
    }
}

// ---------------- launch ----------------
extern "C" void kernel_launch(void* const* d_in, const int* in_sizes, int n_in,
                              void* d_out, int out_size) {
    (void)in_sizes; (void)n_in;
    const float* x   = (const float*)d_in[0];
    const float* wg  = (const float*)d_in[1];
    const float* wig = (const float*)d_in[2];
    const float* wiu = (const float*)d_in[3];
    const float* wo  = (const float*)d_in[4];
    float* out = (float*)d_out;

    const int G1_SMEM = NSTAGE * G1_STAGE;  // 81920 bytes
    const int G2_SMEM = NSTAGE * G2_STAGE;  // 81920 bytes
    cudaFuncSetAttribute(gemm1_kernel, cudaFuncAttributeMaxDynamicSharedMemorySize, G1_SMEM);
    cudaFuncSetAttribute(gemm2_kernel, cudaFuncAttributeMaxDynamicSharedMemorySize, G2_SMEM);

    prep_kernel<<<(PREP_THREADS + 255) / 256, 256>>>(x, wig, wiu, wo, out);
    router_kernel<<<T_TOK / 16, 512>>>(x, wg);
    scan_kernel<<<NE, 1024>>>();
    gemm1_kernel<<<dim3(FF / 64, MAXR / BM, NE), 256, G1_SMEM>>>();
    gemm2_kernel<<<dim3(DIM / 128, MAXR / BM, NE), 256, G2_SMEM>>>(out);
    finalize_kernel<<<1, 1>>>(out, out_size);
}

// round 13
// speedup vs baseline: 1.0155x; 1.0155x over previous
#include <cuda_runtime.h>
#include <cuda_fp16.h>
#include <math.h>
#include <stdint.h>

#define T_TOK 8192
#define DIM   768
#define FF    3072
#define NE    8
#define CAP   2560
#define MAXR  5120   // 2*CAP, max gathered rows per expert

// ---------------- static device scratch ----------------
__device__ __half g_Wg_h[(size_t)NE * FF * DIM];
__device__ __half g_Wu_h[(size_t)NE * FF * DIM];
__device__ __half g_Wo_h[(size_t)NE * DIM * FF];
__device__ __half g_X_h[(size_t)T_TOK * DIM];
__device__ __half g_H_h[(size_t)NE * MAXR * FF];
__device__ int    g_tok[NE * MAXR];
__device__ float  g_wrow[NE * MAXR];   // combine weight per gathered row
__device__ int    g_topk[T_TOK * 2];
__device__ float  g_topp[T_TOK * 2];
__device__ int    g_cnt[NE];

#define ROUTER_BLOCKS (T_TOK / 8)      // 1024 router blocks, 8 tokens each
__device__ float  g_psum_part[ROUTER_BLOCKS * NE];
__device__ int    g_cnta_part[ROUTER_BLOCKS * NE];
__device__ float  g_zsum_part[ROUTER_BLOCKS];

// ---------------- helpers ----------------
__device__ __forceinline__ uint32_t su32(const void* p) {
    uint32_t a;
    asm("{ .reg .u64 t; cvta.to.shared.u64 t, %1; cvt.u32.u64 %0, t; }" : "=r"(a) : "l"(p));
    return a;
}
__device__ __forceinline__ void cp16(uint32_t dst, const void* src) {
    asm volatile("cp.async.cg.shared.global [%0], [%1], 16;" :: "r"(dst), "l"(src) : "memory");
}
#define CP_COMMIT() asm volatile("cp.async.commit_group;" ::: "memory")
#define CP_WAIT_2() asm volatile("cp.async.wait_group 2;" ::: "memory")

#define MMA_F16(D, A, B0, B1)                                                    \
    asm volatile(                                                                \
        "mma.sync.aligned.m16n8k16.row.col.f32.f16.f16.f32 "                     \
        "{%0,%1,%2,%3}, {%4,%5,%6,%7}, {%8,%9}, {%0,%1,%2,%3};\n"                \
        : "+f"((D)[0]), "+f"((D)[1]), "+f"((D)[2]), "+f"((D)[3])                 \
        : "r"((A)[0]), "r"((A)[1]), "r"((A)[2]), "r"((A)[3]), "r"(B0), "r"(B1))

#define LDSM4(R, addr)                                                           \
    asm volatile("ldmatrix.sync.aligned.m8n8.x4.shared.b16 {%0,%1,%2,%3}, [%4];" \
        : "=r"((R)[0]), "=r"((R)[1]), "=r"((R)[2]), "=r"((R)[3]) : "r"(addr))

// ---------------- fused prep: router blocks + out-zero + fp32->fp16 cvt ----------------
#define NX8 ((T_TOK * DIM) / 8)          // 786432 packs (16B fp16 each)
#define NW8 ((NE * FF * DIM) / 8)        // 2359296
#define CVT_TOT (NX8 + 3 * NW8)          // 7864320 packs
#define CVT_HALF (CVT_TOT / 2)           // 3932160 threads, 2 packs each
#define ZERO_THREADS ((T_TOK * DIM) / 8) // 786432 threads, 2 float4 each
#define WORK_THREADS (CVT_HALF + ZERO_THREADS)
#define WORK_BLOCKS  ((WORK_THREADS + 255) / 256)   // 18432

__device__ __forceinline__ uint4 cvt_pack(float4 v0, float4 v1) {
    __half2 h0 = __floats2half2_rn(v0.x, v0.y);
    __half2 h1 = __floats2half2_rn(v0.z, v0.w);
    __half2 h2 = __floats2half2_rn(v1.x, v1.y);
    __half2 h3 = __floats2half2_rn(v1.z, v1.w);
    uint4 o;
    o.x = *(const uint32_t*)&h0; o.y = *(const uint32_t*)&h1;
    o.z = *(const uint32_t*)&h2; o.w = *(const uint32_t*)&h3;
    return o;
}

__global__ void prep_kernel(const float* __restrict__ x,  const float* __restrict__ wig,
                            const float* __restrict__ wiu, const float* __restrict__ wo,
                            const float* __restrict__ wg,  float* __restrict__ out) {
    __shared__ float sg[NE * DIM];
    __shared__ float shp[NE];
    __shared__ int   shc[NE];
    __shared__ float shz;
    int tid = threadIdx.x;

    if (blockIdx.x < ROUTER_BLOCKS) {
        // ---- router branch: 8 tokens per block, 1 warp per token, partial-sum outputs ----
        int blk = blockIdx.x;
        for (int i = tid; i < NE * DIM; i += 256) sg[i] = wg[i];
        if (tid < NE) { shp[tid] = 0.f; shc[tid] = 0; }
        if (tid == 0) shz = 0.f;
        __syncthreads();

        int w = tid >> 5, lane = tid & 31;
        int t = blk * 8 + w;
        const float* xt = x + (size_t)t * DIM;
        float acc[NE];
#pragma unroll
        for (int e = 0; e < NE; e++) acc[e] = 0.f;
        for (int j = lane; j < DIM; j += 32) {
            float xv = xt[j];
#pragma unroll
            for (int e = 0; e < NE; e++) acc[e] += xv * sg[e * DIM + j];
        }
#pragma unroll
        for (int o = 16; o > 0; o >>= 1) {
#pragma unroll
            for (int e = 0; e < NE; e++) acc[e] += __shfl_xor_sync(0xffffffffu, acc[e], o);
        }
        if (lane == 0) {
            float m = acc[0];
#pragma unroll
            for (int e = 1; e < NE; e++) m = fmaxf(m, acc[e]);
            float p[NE]; float s = 0.f;
#pragma unroll
            for (int e = 0; e < NE; e++) { p[e] = expf(acc[e] - m); s += p[e]; }
            float inv = 1.f / s;
#pragma unroll
            for (int e = 0; e < NE; e++) p[e] *= inv;
            float lse = m + logf(s);
            int i0 = 0; float b0 = p[0];
#pragma unroll
            for (int e = 1; e < NE; e++) if (p[e] > b0) { b0 = p[e]; i0 = e; }
            int i1 = -1; float b1 = -1.f;
#pragma unroll
            for (int e = 0; e < NE; e++) if (e != i0 && p[e] > b1) { b1 = p[e]; i1 = e; }
            float invs = 1.f / (b0 + b1);
            g_topk[t * 2] = i0; g_topk[t * 2 + 1] = i1;
            g_topp[t * 2] = b0 * invs; g_topp[t * 2 + 1] = b1 * invs;
#pragma unroll
            for (int e = 0; e < NE; e++) atomicAdd(&shp[e], p[e]);
            atomicAdd(&shc[i0], 1);
            atomicAdd(&shc[i1], 1);
            atomicAdd(&shz, lse * lse);
        }
        __syncthreads();
        if (tid < NE) {
            g_psum_part[blk * NE + tid] = shp[tid];
            g_cnta_part[blk * NE + tid] = shc[tid];
        }
        if (tid == 0) g_zsum_part[blk] = shz;
        return;
    }

    // ---- cvt / zero branch ----
    int i = (blockIdx.x - ROUTER_BLOCKS) * 256 + tid;
    if (i < CVT_HALF) {
        int j = 2 * i;
        const float* s;
        __half* d;
        int k;
        if (j < NX8)                { s = x;   d = g_X_h;  k = j; }
        else if (j < NX8 + NW8)     { s = wig; d = g_Wg_h; k = j - NX8; }
        else if (j < NX8 + 2 * NW8) { s = wiu; d = g_Wu_h; k = j - NX8 - NW8; }
        else                        { s = wo;  d = g_Wo_h; k = j - NX8 - 2 * NW8; }
        float4 v0 = ((const float4*)s)[2 * k];
        float4 v1 = ((const float4*)s)[2 * k + 1];
        float4 v2 = ((const float4*)s)[2 * k + 2];
        float4 v3 = ((const float4*)s)[2 * k + 3];
        ((uint4*)d)[k]     = cvt_pack(v0, v1);
        ((uint4*)d)[k + 1] = cvt_pack(v2, v3);
    } else if (i < WORK_THREADS) {
        int z = i - CVT_HALF;
        float4 zz = make_float4(0.f, 0.f, 0.f, 0.f);
        ((float4*)out)[2 * z]     = zz;
        ((float4*)out)[2 * z + 1] = zz;
    }
}

// ---------------- scan: 1024 threads, 8 stripes ----------------
__global__ void scan_kernel() {
    int e = blockIdx.x;
    int tid = threadIdx.x;
    int w = tid >> 5, lane = tid & 31;
    unsigned ltm = (1u << lane) - 1u;
    __shared__ int sw0[32], sw1[32], sws[32];
    __shared__ int base0, base1, baseS;
    if (tid == 0) { base0 = 0; base1 = 0; baseS = 0; }
    __syncthreads();
    for (int b = 0; b < T_TOK; b += 1024) {
        int t = b + tid;
        int i0 = g_topk[t * 2], i1 = g_topk[t * 2 + 1];
        int a0 = (i0 == e) ? 1 : 0;
        int a1 = (i1 == e) ? 1 : 0;
        unsigned m0b = __ballot_sync(0xffffffffu, a0);
        unsigned m1b = __ballot_sync(0xffffffffu, a1);
        if (lane == 0) { sw0[w] = __popc(m0b); sw1[w] = __popc(m1b); }
        __syncthreads();
        int off0 = base0, off1 = base1;
        for (int j = 0; j < w; j++) { off0 += sw0[j]; off1 += sw1[j]; }
        int r0 = off0 + __popc(m0b & ltm);
        int r1 = off1 + __popc(m1b & ltm);
        int k0 = a0 && (r0 < CAP);
        int k1 = a1 && (r1 < CAP);
        int sel = (k0 || k1) ? 1 : 0;
        unsigned msb = __ballot_sync(0xffffffffu, sel);
        if (lane == 0) sws[w] = __popc(msb);
        __syncthreads();
        int offS = baseS;
        for (int j = 0; j < w; j++) offS += sws[j];
        int pos = offS + __popc(msb & ltm);
        if (sel) {
            g_tok[e * MAXR + pos] = t;
            g_wrow[e * MAXR + pos] = k0 ? g_topp[t * 2] : g_topp[t * 2 + 1];
        }
        __syncthreads();
        if (tid == 0) {
            int t0 = 0, t1 = 0, ts = 0;
            for (int j = 0; j < 32; j++) { t0 += sw0[j]; t1 += sw1[j]; ts += sws[j]; }
            base0 += t0; base1 += t1; baseS += ts;
        }
        __syncthreads();
    }
    if (tid == 0) g_cnt[e] = baseS;
}

// ---------------- GEMM config (round-10 proven best; frozen) ----------------
#define BM 128
#define BK 32                  // halves per k-tile (2 x k16 mma steps)
#define LDH 40                 // halves per smem row (32 data + 8 pad), LDSM-conflict-free
#define G1_STAGE 20480u        // bytes: A(128x40x2=10240) + G(64x40x2=5120) + U(5120)
#define G1_GOFF  10240u
#define G1_UOFF  15360u
#define G2_STAGE 20480u        // bytes: A(10240) + B(128x40x2=10240)
#define G2_BOFF  10240u
#define NSTAGE 4

// GEMM1: H = silu(Xg @ Wg^T) * (Xg @ Wu^T); BM=128, BN=64 (per matrix)
// warps 4(m) x 2(n), warp tile 32x32, LDSM fragments, 2 CTAs/SM
__global__ __launch_bounds__(256, 2) void gemm1_kernel() {
    int e = blockIdx.z;
    int cnt = g_cnt[e];
    int m0 = blockIdx.y * BM;
    if (m0 >= cnt) return;
    int n0 = blockIdx.x * 64;

    extern __shared__ __half sm[];
    __shared__ int stok[BM];
    int tid = threadIdx.x;
    if (tid < BM) { int r = m0 + tid; stok[tid] = (r < cnt) ? g_tok[e * MAXR + r] : 0; }
    __syncthreads();

    uint32_t sb = su32(sm);
    int rr = tid >> 1;
    int ko = (tid & 1) * 16;
    const __half* srcA = g_X_h + (size_t)stok[rr] * DIM + ko;
    uint32_t dstA = sb + (uint32_t)(rr * LDH + ko) * 2;
    int bro = (tid & 127) >> 1;   // 0..63
    const __half* srcB = ((tid < 128) ? g_Wg_h : g_Wu_h) + ((size_t)e * FF + n0 + bro) * DIM + ko;
    uint32_t dstB = sb + ((tid < 128) ? G1_GOFF : G1_UOFF) + (uint32_t)(bro * LDH + ko) * 2;

#define G1_ISSUE(s, kt) do {                                           \
        uint32_t b_ = (uint32_t)(s) * G1_STAGE;                        \
        int kh_ = (kt) * BK;                                           \
        cp16(dstA + b_, srcA + kh_); cp16(dstA + b_ + 16, srcA + kh_ + 8); \
        cp16(dstB + b_, srcB + kh_); cp16(dstB + b_ + 16, srcB + kh_ + 8); \
    } while (0)

    int lane = tid & 31, wid = tid >> 5;
    int g = lane >> 2, t4 = lane & 3;
    int wm = wid & 3, wn = wid >> 2;   // 4 x 2 warp grid

    uint32_t offA[2], offB[2];
#pragma unroll
    for (int im = 0; im < 2; im++)
        offA[im] = (uint32_t)((wm * 32 + im * 16 + (lane & 15)) * LDH + (lane >> 4) * 8) * 2;
#pragma unroll
    for (int p = 0; p < 2; p++)
        offB[p] = G1_GOFF + (uint32_t)((wn * 32 + (p * 2 + (lane >> 4)) * 8 + (lane & 7)) * LDH
                                       + ((lane >> 3) & 1) * 8) * 2;

    float ag[2][4][4], au[2][4][4];
#pragma unroll
    for (int i = 0; i < 2; i++)
#pragma unroll
        for (int j = 0; j < 4; j++)
#pragma unroll
            for (int c = 0; c < 4; c++) { ag[i][j][c] = 0.f; au[i][j][c] = 0.f; }

    G1_ISSUE(0, 0); CP_COMMIT();
    G1_ISSUE(1, 1); CP_COMMIT();
    G1_ISSUE(2, 2); CP_COMMIT();

    const int NK = DIM / BK;  // 24
    for (int kt = 0; kt < NK; kt++) {
        CP_WAIT_2();
        __syncthreads();
        if (kt + 3 < NK) G1_ISSUE((kt + 3) % NSTAGE, kt + 3);
        CP_COMMIT();
        uint32_t stb = sb + (uint32_t)(kt % NSTAGE) * G1_STAGE;
#pragma unroll
        for (int km = 0; km < 2; km++) {
            uint32_t kmo = km * 32;
            uint32_t a[2][4], gq[2][4], uq[2][4];
            LDSM4(a[0], stb + offA[0] + kmo);
            LDSM4(a[1], stb + offA[1] + kmo);
            LDSM4(gq[0], stb + offB[0] + kmo);
            LDSM4(gq[1], stb + offB[1] + kmo);
            LDSM4(uq[0], stb + offB[0] + (G1_UOFF - G1_GOFF) + kmo);
            LDSM4(uq[1], stb + offB[1] + (G1_UOFF - G1_GOFF) + kmo);
#pragma unroll
            for (int p = 0; p < 2; p++) {
#pragma unroll
                for (int s = 0; s < 2; s++) {
                    int jn = p * 2 + s;
#pragma unroll
                    for (int im = 0; im < 2; im++) {
                        MMA_F16(ag[im][jn], a[im], gq[p][s * 2], gq[p][s * 2 + 1]);
                        MMA_F16(au[im][jn], a[im], uq[p][s * 2], uq[p][s * 2 + 1]);
                    }
                }
            }
        }
    }

    // epilogue: h = silu(g) * u, store fp16 H
#pragma unroll
    for (int im = 0; im < 2; im++) {
#pragma unroll
        for (int jn = 0; jn < 4; jn++) {
            int rl  = wm * 32 + im * 16 + g;
            int col = n0 + wn * 32 + jn * 8 + t4 * 2;
            size_t b0i = (size_t)(e * MAXR + m0 + rl) * FF + col;
            size_t b1i = (size_t)(e * MAXR + m0 + rl + 8) * FF + col;
            float gg, uu, h0x, h0y, h1x, h1y;
            gg = ag[im][jn][0]; uu = au[im][jn][0]; h0x = gg / (1.f + expf(-gg)) * uu;
            gg = ag[im][jn][1]; uu = au[im][jn][1]; h0y = gg / (1.f + expf(-gg)) * uu;
            gg = ag[im][jn][2]; uu = au[im][jn][2]; h1x = gg / (1.f + expf(-gg)) * uu;
            gg = ag[im][jn][3]; uu = au[im][jn][3]; h1y = gg / (1.f + expf(-gg)) * uu;
            *(__half2*)&g_H_h[b0i] = __floats2half2_rn(h0x, h0y);
            *(__half2*)&g_H_h[b1i] = __floats2half2_rn(h1x, h1y);
        }
    }
}

// GEMM2 + fused combine: out[tok] += w * (H @ Wo^T); BM=128, BN=128, warps 4x2, 2 CTAs/SM
__global__ __launch_bounds__(256, 2) void gemm2_kernel(float* __restrict__ out) {
    int e = blockIdx.z;
    int cnt = g_cnt[e];
    int m0 = blockIdx.y * BM;
    if (m0 >= cnt) return;
    int n0 = blockIdx.x * 128;

    extern __shared__ __half sm[];
    __shared__ int   stok[BM];
    __shared__ float swt[BM];
    int tid = threadIdx.x;
    if (tid < BM) {
        int r = m0 + tid;
        bool v = r < cnt;
        stok[tid] = v ? g_tok[e * MAXR + r] : 0;
        swt[tid]  = v ? g_wrow[e * MAXR + r] : 0.f;
    }

    uint32_t sb = su32(sm);
    int rr = tid >> 1;
    int ko = (tid & 1) * 16;
    const __half* srcA = g_H_h + (size_t)(e * MAXR + m0 + rr) * FF + ko;
    uint32_t dstA = sb + (uint32_t)(rr * LDH + ko) * 2;
    const __half* srcB = g_Wo_h + ((size_t)e * DIM + n0 + rr) * FF + ko;
    uint32_t dstB = sb + G2_BOFF + (uint32_t)(rr * LDH + ko) * 2;

#define G2_ISSUE(s, kt) do {                                           \
        uint32_t b_ = (uint32_t)(s) * G2_STAGE;                        \
        int kh_ = (kt) * BK;                                           \
        cp16(dstA + b_, srcA + kh_); cp16(dstA + b_ + 16, srcA + kh_ + 8); \
        cp16(dstB + b_, srcB + kh_); cp16(dstB + b_ + 16, srcB + kh_ + 8); \
    } while (0)

    int lane = tid & 31, wid = tid >> 5;
    int g = lane >> 2, t4 = lane & 3;
    int wm = wid & 3, wn = wid >> 2;

    uint32_t offA[2], offB[4];
#pragma unroll
    for (int im = 0; im < 2; im++)
        offA[im] = (uint32_t)((wm * 32 + im * 16 + (lane & 15)) * LDH + (lane >> 4) * 8) * 2;
#pragma unroll
    for (int p = 0; p < 4; p++)
        offB[p] = G2_BOFF + (uint32_t)((wn * 64 + (p * 2 + (lane >> 4)) * 8 + (lane & 7)) * LDH
                                       + ((lane >> 3) & 1) * 8) * 2;

    float acc[2][8][4];
#pragma unroll
    for (int i = 0; i < 2; i++)
#pragma unroll
        for (int j = 0; j < 8; j++)
#pragma unroll
            for (int c = 0; c < 4; c++) acc[i][j][c] = 0.f;

    G2_ISSUE(0, 0); CP_COMMIT();
    G2_ISSUE(1, 1); CP_COMMIT();
    G2_ISSUE(2, 2); CP_COMMIT();

    const int NK = FF / BK;  // 96
    for (int kt = 0; kt < NK; kt++) {
        CP_WAIT_2();
        __syncthreads();
        if (kt + 3 < NK) G2_ISSUE((kt + 3) % NSTAGE, kt + 3);
        CP_COMMIT();
        uint32_t stb = sb + (uint32_t)(kt % NSTAGE) * G2_STAGE;
#pragma unroll
        for (int km = 0; km < 2; km++) {
            uint32_t kmo = km * 32;
            uint32_t a[2][4], bq[4][4];
            LDSM4(a[0], stb + offA[0] + kmo);
            LDSM4(a[1], stb + offA[1] + kmo);
#pragma unroll
            for (int p = 0; p < 4; p++) LDSM4(bq[p], stb + offB[p] + kmo);
#pragma unroll
            for (int p = 0; p < 4; p++) {
#pragma unroll
                for (int s = 0; s < 2; s++) {
                    int jn = p * 2 + s;
#pragma unroll
                    for (int im = 0; im < 2; im++)
                        MMA_F16(acc[im][jn], a[im], bq[p][s * 2], bq[p][s * 2 + 1]);
                }
            }
        }
    }

    // fused combine epilogue: out[tok, col] += w * acc  (<=2 commutative contributions
    // per element -> order-independent -> deterministic)
#pragma unroll
    for (int im = 0; im < 2; im++) {
        int rl0 = wm * 32 + im * 16 + g;
        int rl1 = rl0 + 8;
        int tok0 = stok[rl0]; float w0 = swt[rl0];
        int tok1 = stok[rl1]; float w1 = swt[rl1];
        float* o0 = out + (size_t)tok0 * DIM;
        float* o1 = out + (size_t)tok1 * DIM;
#pragma unroll
        for (int jn = 0; jn < 8; jn++) {
            int col = n0 + wn * 64 + jn * 8 + t4 * 2;
            if (w0 > 0.f) {
                atomicAdd(o0 + col,     w0 * acc[im][jn][0]);
                atomicAdd(o0 + col + 1, w0 * acc[im][jn][1]);
            }
            if (w1 > 0.f) {
                atomicAdd(o1 + col,     w1 * acc[im][jn][2]);
                atomicAdd(o1 + col + 1, w1 * acc[im][jn][3]);
            }
        }
    }
}

// ---------------- finalize: parallel reduction of router partials + aux loss ----------------
__global__ void finalize_kernel(float* __restrict__ out, int out_size) {
    if (out_size <= T_TOK * DIM) return;
    __shared__ float wp[32][NE];
    __shared__ int   wc[32][NE];
    __shared__ float wz[32];
    int tid = threadIdx.x;        // 1024 threads; one per router block
    int lane = tid & 31, w = tid >> 5;

    float p[NE]; int c[NE];
#pragma unroll
    for (int e = 0; e < NE; e++) {
        p[e] = g_psum_part[tid * NE + e];
        c[e] = g_cnta_part[tid * NE + e];
    }
    float z = g_zsum_part[tid];
#pragma unroll
    for (int o = 16; o > 0; o >>= 1) {
#pragma unroll
        for (int e = 0; e < NE; e++) {
            p[e] += __shfl_xor_sync(0xffffffffu, p[e], o);
            c[e] += __shfl_xor_sync(0xffffffffu, c[e], o);
        }
        z += __shfl_xor_sync(0xffffffffu, z, o);
    }
    if (lane == 0) {
#pragma unroll
        for (int e = 0; e < NE; e++) { wp[w][e] = p[e]; wc[w][e] = c[e]; }
        wz[w] = z;
    }
    __syncthreads();
    if (w == 0) {
#pragma unroll
        for (int e = 0; e < NE; e++) { p[e] = wp[lane][e]; c[e] = (float)0, c[e] = wc[lane][e]; }
        z = wz[lane];
#pragma unroll
        for (int o = 16; o > 0; o >>= 1) {
#pragma unroll
            for (int e = 0; e < NE; e++) {
                p[e] += __shfl_xor_sync(0xffffffffu, p[e], o);
                c[e] += __shfl_xor_sync(0xffffffffu, c[e], o);
            }
            z += __shfl_xor_sync(0xffffffffu, z, o);
        }
        if (lane == 0) {
            float lb = 0.f;
#pragma unroll
            for (int e = 0; e < NE; e++) {
                float f = (float)c[e] / (float)(T_TOK * 2);
                float P = p[e] / (float)T_TOK;
                lb += f * P;
            }
            lb *= (float)NE;
            out[T_TOK * DIM] = 0.01f * lb + 0.001f * (z / (float)T_TOK);
        }
    }
}

// ---------------- launch ----------------
extern "C" void kernel_launch(void* const* d_in, const int* in_sizes, int n_in,
                              void* d_out, int out_size) {
    (void)in_sizes; (void)n_in;
    const float* x   = (const float*)d_in[0];
    const float* wg  = (const float*)d_in[1];
    const float* wig = (const float*)d_in[2];
    const float* wiu = (const float*)d_in[3];
    const float* wo  = (const float*)d_in[4];
    float* out = (float*)d_out;

    const int G1_SMEM = NSTAGE * G1_STAGE;  // 81920 bytes
    const int G2_SMEM = NSTAGE * G2_STAGE;  // 81920 bytes
    cudaFuncSetAttribute(gemm1_kernel, cudaFuncAttributeMaxDynamicSharedMemorySize, G1_SMEM);
    cudaFuncSetAttribute(gemm2_kernel, cudaFuncAttributeMaxDynamicSharedMemorySize, G2_SMEM);

    prep_kernel<<<ROUTER_BLOCKS + WORK_BLOCKS, 256>>>(x, wig, wiu, wo, wg, out);
    scan_kernel<<<NE, 1024>>>();
    gemm1_kernel<<<dim3(FF / 64, MAXR / BM, NE), 256, G1_SMEM>>>();
    gemm2_kernel<<<dim3(DIM / 128, MAXR / BM, NE), 256, G2_SMEM>>>(out);
    finalize_kernel<<<1, 1024>>>(out, out_size);
}

// round 15
// speedup vs baseline: 1.0311x; 1.0154x over previous
#include <cuda_runtime.h>
#include <cuda_fp16.h>
#include <math.h>
#include <stdint.h>

#define T_TOK 8192
#define DIM   768
#define FF    3072
#define NE    8
#define CAP   2560
#define MAXR  5120   // 2*CAP, max gathered rows per expert

// ---------------- static device scratch ----------------
__device__ __half g_Wg_h[(size_t)NE * FF * DIM];
__device__ __half g_Wu_h[(size_t)NE * FF * DIM];
__device__ __half g_Wo_h[(size_t)NE * DIM * FF];
__device__ __half g_X_h[(size_t)T_TOK * DIM];
__device__ __half g_H_h[(size_t)NE * MAXR * FF];
__device__ int    g_tok[NE * MAXR];
__device__ float  g_wrow[NE * MAXR];   // combine weight per gathered row
__device__ int    g_topk[T_TOK * 2];
__device__ float  g_topp[T_TOK * 2];
__device__ int    g_cnt[NE];
__device__ int    g_cnta[NE];
__device__ float  g_psum[NE];
__device__ float  g_zsum;
__device__ int    g_work1;             // persistent-GEMM tile counters
__device__ int    g_work2;

// ---------------- helpers ----------------
__device__ __forceinline__ uint32_t su32(const void* p) {
    uint32_t a;
    asm("{ .reg .u64 t; cvta.to.shared.u64 t, %1; cvt.u32.u64 %0, t; }" : "=r"(a) : "l"(p));
    return a;
}
__device__ __forceinline__ void cp16(uint32_t dst, const void* src) {
    asm volatile("cp.async.cg.shared.global [%0], [%1], 16;" :: "r"(dst), "l"(src) : "memory");
}
#define CP_COMMIT() asm volatile("cp.async.commit_group;" ::: "memory")
#define CP_WAIT_2() asm volatile("cp.async.wait_group 2;" ::: "memory")
#define CP_WAIT_0() asm volatile("cp.async.wait_group 0;" ::: "memory")

#define MMA_F16(D, A, B0, B1)                                                    \
    asm volatile(                                                                \
        "mma.sync.aligned.m16n8k16.row.col.f32.f16.f16.f32 "                     \
        "{%0,%1,%2,%3}, {%4,%5,%6,%7}, {%8,%9}, {%0,%1,%2,%3};\n"                \
        : "+f"((D)[0]), "+f"((D)[1]), "+f"((D)[2]), "+f"((D)[3])                 \
        : "r"((A)[0]), "r"((A)[1]), "r"((A)[2]), "r"((A)[3]), "r"(B0), "r"(B1))

#define LDSM4(R, addr)                                                           \
    asm volatile("ldmatrix.sync.aligned.m8n8.x4.shared.b16 {%0,%1,%2,%3}, [%4];" \
        : "=r"((R)[0]), "=r"((R)[1]), "=r"((R)[2]), "=r"((R)[3]) : "r"(addr))

// ---------------- fused prep: aux-zero + out-zero + fp32->fp16 cvt ----------------
#define NX8 ((T_TOK * DIM) / 8)          // 786432 packs (16B fp16 each)
#define NW8 ((NE * FF * DIM) / 8)        // 2359296
#define CVT_TOT (NX8 + 3 * NW8)          // 7864320 packs
#define CVT_HALF (CVT_TOT / 2)           // 3932160 threads, 2 packs each
#define ZERO_THREADS ((T_TOK * DIM) / 8) // 786432 threads, 2 float4 each
#define PREP_THREADS (CVT_HALF + ZERO_THREADS)

__device__ __forceinline__ uint4 cvt_pack(float4 v0, float4 v1) {
    __half2 h0 = __floats2half2_rn(v0.x, v0.y);
    __half2 h1 = __floats2half2_rn(v0.z, v0.w);
    __half2 h2 = __floats2half2_rn(v1.x, v1.y);
    __half2 h3 = __floats2half2_rn(v1.z, v1.w);
    uint4 o;
    o.x = *(const uint32_t*)&h0; o.y = *(const uint32_t*)&h1;
    o.z = *(const uint32_t*)&h2; o.w = *(const uint32_t*)&h3;
    return o;
}

__global__ void prep_kernel(const float* __restrict__ x,  const float* __restrict__ wig,
                            const float* __restrict__ wiu, const float* __restrict__ wo,
                            float* __restrict__ out) {
    int i = blockIdx.x * blockDim.x + threadIdx.x;
    if (i < CVT_HALF) {
        int j = 2 * i;
        const float* s;
        __half* d;
        int k;
        if (j < NX8)                { s = x;   d = g_X_h;  k = j; }
        else if (j < NX8 + NW8)     { s = wig; d = g_Wg_h; k = j - NX8; }
        else if (j < NX8 + 2 * NW8) { s = wiu; d = g_Wu_h; k = j - NX8 - NW8; }
        else                        { s = wo;  d = g_Wo_h; k = j - NX8 - 2 * NW8; }
        float4 v0 = ((const float4*)s)[2 * k];
        float4 v1 = ((const float4*)s)[2 * k + 1];
        float4 v2 = ((const float4*)s)[2 * k + 2];
        float4 v3 = ((const float4*)s)[2 * k + 3];
        ((uint4*)d)[k]     = cvt_pack(v0, v1);
        ((uint4*)d)[k + 1] = cvt_pack(v2, v3);
    } else if (i < PREP_THREADS) {
        int z = i - CVT_HALF;
        float4 zz = make_float4(0.f, 0.f, 0.f, 0.f);
        ((float4*)out)[2 * z]     = zz;
        ((float4*)out)[2 * z + 1] = zz;
        if (z == 0) {
#pragma unroll
            for (int e = 0; e < NE; e++) { g_psum[e] = 0.f; g_cnta[e] = 0; }
            g_zsum = 0.f;
            g_work1 = 0;
            g_work2 = 0;
        }
    }
}

// ---------------- router: 512 threads (16 tokens/block) ----------------
__global__ void router_kernel(const float* __restrict__ x, const float* __restrict__ wg) {
    __shared__ float sg[NE * DIM];
    __shared__ float shp[NE];
    __shared__ int   shc[NE];
    __shared__ float shz;
    int tid = threadIdx.x;
    for (int i = tid; i < NE * DIM; i += 512) sg[i] = wg[i];
    if (tid < NE) { shp[tid] = 0.f; shc[tid] = 0; }
    if (tid == 0) shz = 0.f;
    __syncthreads();

    int w = tid >> 5, lane = tid & 31;
    int t = blockIdx.x * 16 + w;
    const float* xt = x + (size_t)t * DIM;
    float acc[NE];
#pragma unroll
    for (int e = 0; e < NE; e++) acc[e] = 0.f;
    for (int j = lane; j < DIM; j += 32) {
        float xv = xt[j];
#pragma unroll
        for (int e = 0; e < NE; e++) acc[e] += xv * sg[e * DIM + j];
    }
#pragma unroll
    for (int o = 16; o > 0; o >>= 1) {
#pragma unroll
        for (int e = 0; e < NE; e++) acc[e] += __shfl_xor_sync(0xffffffffu, acc[e], o);
    }
    if (lane == 0) {
        float m = acc[0];
#pragma unroll
        for (int e = 1; e < NE; e++) m = fmaxf(m, acc[e]);
        float p[NE]; float s = 0.f;
#pragma unroll
        for (int e = 0; e < NE; e++) { p[e] = expf(acc[e] - m); s += p[e]; }
        float inv = 1.f / s;
#pragma unroll
        for (int e = 0; e < NE; e++) p[e] *= inv;
        float lse = m + logf(s);
        int i0 = 0; float b0 = p[0];
#pragma unroll
        for (int e = 1; e < NE; e++) if (p[e] > b0) { b0 = p[e]; i0 = e; }
        int i1 = -1; float b1 = -1.f;
#pragma unroll
        for (int e = 0; e < NE; e++) if (e != i0 && p[e] > b1) { b1 = p[e]; i1 = e; }
        float invs = 1.f / (b0 + b1);
        g_topk[t * 2] = i0; g_topk[t * 2 + 1] = i1;
        g_topp[t * 2] = b0 * invs; g_topp[t * 2 + 1] = b1 * invs;
#pragma unroll
        for (int e = 0; e < NE; e++) atomicAdd(&shp[e], p[e]);
        atomicAdd(&shc[i0], 1);
        atomicAdd(&shc[i1], 1);
        atomicAdd(&shz, lse * lse);
    }
    __syncthreads();
    if (tid < NE) { atomicAdd(&g_psum[tid], shp[tid]); atomicAdd(&g_cnta[tid], shc[tid]); }
    if (tid == 0) atomicAdd(&g_zsum, shz);
}

// ---------------- scan: 1024 threads, 8 stripes ----------------
__global__ void scan_kernel() {
    int e = blockIdx.x;
    int tid = threadIdx.x;
    int w = tid >> 5, lane = tid & 31;
    unsigned ltm = (1u << lane) - 1u;
    __shared__ int sw0[32], sw1[32], sws[32];
    __shared__ int base0, base1, baseS;
    if (tid == 0) { base0 = 0; base1 = 0; baseS = 0; }
    __syncthreads();
    for (int b = 0; b < T_TOK; b += 1024) {
        int t = b + tid;
        int i0 = g_topk[t * 2], i1 = g_topk[t * 2 + 1];
        int a0 = (i0 == e) ? 1 : 0;
        int a1 = (i1 == e) ? 1 : 0;
        unsigned m0b = __ballot_sync(0xffffffffu, a0);
        unsigned m1b = __ballot_sync(0xffffffffu, a1);
        if (lane == 0) { sw0[w] = __popc(m0b); sw1[w] = __popc(m1b); }
        __syncthreads();
        int off0 = base0, off1 = base1;
        for (int j = 0; j < w; j++) { off0 += sw0[j]; off1 += sw1[j]; }
        int r0 = off0 + __popc(m0b & ltm);
        int r1 = off1 + __popc(m1b & ltm);
        int k0 = a0 && (r0 < CAP);
        int k1 = a1 && (r1 < CAP);
        int sel = (k0 || k1) ? 1 : 0;
        unsigned msb = __ballot_sync(0xffffffffu, sel);
        if (lane == 0) sws[w] = __popc(msb);
        __syncthreads();
        int offS = baseS;
        for (int j = 0; j < w; j++) offS += sws[j];
        int pos = offS + __popc(msb & ltm);
        if (sel) {
            g_tok[e * MAXR + pos] = t;
            g_wrow[e * MAXR + pos] = k0 ? g_topp[t * 2] : g_topp[t * 2 + 1];
        }
        __syncthreads();
        if (tid == 0) {
            int t0 = 0, t1 = 0, ts = 0;
            for (int j = 0; j < 32; j++) { t0 += sw0[j]; t1 += sw1[j]; ts += sws[j]; }
            base0 += t0; base1 += t1; baseS += ts;
        }
        __syncthreads();
    }
    if (tid == 0) g_cnt[e] = baseS;
}

// ---------------- GEMM config (round-10 proven inner loops; persistent scheduling) ----------------
#define BM 128
#define BK 32                  // halves per k-tile (2 x k16 mma steps)
#define LDH 40                 // halves per smem row (32 data + 8 pad), LDSM-conflict-free
#define G1_STAGE 20480u        // bytes: A(128x40x2=10240) + G(64x40x2=5120) + U(5120)
#define G1_GOFF  10240u
#define G1_UOFF  15360u
#define G2_STAGE 20480u        // bytes: A(10240) + B(128x40x2=10240)
#define G2_BOFF  10240u
#define NSTAGE 4
#define G1_NT (FF / 64)        // 48 n-tiles per expert row-block
#define G2_NT (DIM / 128)      // 6
#define PERSIST_CTAS 304       // 2 per SM on 152-SM GB300

// GEMM1 (persistent): H = silu(Xg @ Wg^T) * (Xg @ Wu^T)
__global__ __launch_bounds__(256, 2) void gemm1_kernel() {
    extern __shared__ __half sm[];
    __shared__ int stok[BM];
    __shared__ int s_nb[NE];
    __shared__ int s_tile;
    int tid = threadIdx.x;
    if (tid < NE) s_nb[tid] = ((g_cnt[tid] + BM - 1) / BM) * G1_NT;
    __syncthreads();
    int tot = 0;
#pragma unroll
    for (int e = 0; e < NE; e++) tot += s_nb[e];

    uint32_t sb = su32(sm);
    int rr = tid >> 1;
    int ko = (tid & 1) * 16;
    uint32_t dstA = sb + (uint32_t)(rr * LDH + ko) * 2;
    int bro = (tid & 127) >> 1;   // 0..63
    uint32_t dstB = sb + ((tid < 128) ? G1_GOFF : G1_UOFF) + (uint32_t)(bro * LDH + ko) * 2;

    int lane = tid & 31, wid = tid >> 5;
    int g = lane >> 2, t4 = lane & 3;
    int wm = wid & 3, wn = wid >> 2;   // 4 x 2 warp grid

    uint32_t offA[2], offB[2];
#pragma unroll
    for (int im = 0; im < 2; im++)
        offA[im] = (uint32_t)((wm * 32 + im * 16 + (lane & 15)) * LDH + (lane >> 4) * 8) * 2;
#pragma unroll
    for (int p = 0; p < 2; p++)
        offB[p] = G1_GOFF + (uint32_t)((wn * 32 + (p * 2 + (lane >> 4)) * 8 + (lane & 7)) * LDH
                                       + ((lane >> 3) & 1) * 8) * 2;

    for (;;) {
        if (tid == 0) s_tile = atomicAdd(&g_work1, 1);
        __syncthreads();
        int t = s_tile;
        if (t >= tot) break;
        int e = 0, base = 0;
        while (t >= base + s_nb[e]) { base += s_nb[e]; e++; }
        int loc = t - base;
        int m0 = (loc / G1_NT) * BM;
        int n0 = (loc % G1_NT) * 64;
        int cnt = g_cnt[e];
        if (tid < BM) { int r = m0 + tid; stok[tid] = (r < cnt) ? g_tok[e * MAXR + r] : 0; }
        __syncthreads();

        const __half* srcA = g_X_h + (size_t)stok[rr] * DIM + ko;
        const __half* srcB = ((tid < 128) ? g_Wg_h : g_Wu_h)
                             + ((size_t)e * FF + n0 + bro) * DIM + ko;

#define G1_ISSUE(s, kt) do {                                           \
        uint32_t b_ = (uint32_t)(s) * G1_STAGE;                        \
        int kh_ = (kt) * BK;                                           \
        cp16(dstA + b_, srcA + kh_); cp16(dstA + b_ + 16, srcA + kh_ + 8); \
        cp16(dstB + b_, srcB + kh_); cp16(dstB + b_ + 16, srcB + kh_ + 8); \
    } while (0)

        float ag[2][4][4], au[2][4][4];
#pragma unroll
        for (int i = 0; i < 2; i++)
#pragma unroll
            for (int j = 0; j < 4; j++)
#pragma unroll
                for (int c = 0; c < 4; c++) { ag[i][j][c] = 0.f; au[i][j][c] = 0.f; }

        G1_ISSUE(0, 0); CP_COMMIT();
        G1_ISSUE(1, 1); CP_COMMIT();
        G1_ISSUE(2, 2); CP_COMMIT();

        const int NK = DIM / BK;  // 24
        for (int kt = 0; kt < NK; kt++) {
            CP_WAIT_2();
            __syncthreads();
            if (kt + 3 < NK) G1_ISSUE((kt + 3) % NSTAGE, kt + 3);
            CP_COMMIT();
            uint32_t stb = sb + (uint32_t)(kt % NSTAGE) * G1_STAGE;
#pragma unroll
            for (int km = 0; km < 2; km++) {
                uint32_t kmo = km * 32;
                uint32_t a[2][4], gq[2][4], uq[2][4];
                LDSM4(a[0], stb + offA[0] + kmo);
                LDSM4(a[1], stb + offA[1] + kmo);
                LDSM4(gq[0], stb + offB[0] + kmo);
                LDSM4(gq[1], stb + offB[1] + kmo);
                LDSM4(uq[0], stb + offB[0] + (G1_UOFF - G1_GOFF) + kmo);
                LDSM4(uq[1], stb + offB[1] + (G1_UOFF - G1_GOFF) + kmo);
#pragma unroll
                for (int p = 0; p < 2; p++) {
#pragma unroll
                    for (int s = 0; s < 2; s++) {
                        int jn = p * 2 + s;
#pragma unroll
                        for (int im = 0; im < 2; im++) {
                            MMA_F16(ag[im][jn], a[im], gq[p][s * 2], gq[p][s * 2 + 1]);
                            MMA_F16(au[im][jn], a[im], uq[p][s * 2], uq[p][s * 2 + 1]);
                        }
                    }
                }
            }
        }

        // epilogue: h = silu(g) * u, store fp16 H
#pragma unroll
        for (int im = 0; im < 2; im++) {
#pragma unroll
            for (int jn = 0; jn < 4; jn++) {
                int rl  = wm * 32 + im * 16 + g;
                int col = n0 + wn * 32 + jn * 8 + t4 * 2;
                size_t b0i = (size_t)(e * MAXR + m0 + rl) * FF + col;
                size_t b1i = (size_t)(e * MAXR + m0 + rl + 8) * FF + col;
                float gg, uu, h0x, h0y, h1x, h1y;
                gg = ag[im][jn][0]; uu = au[im][jn][0]; h0x = gg / (1.f + expf(-gg)) * uu;
                gg = ag[im][jn][1]; uu = au[im][jn][1]; h0y = gg / (1.f + expf(-gg)) * uu;
                gg = ag[im][jn][2]; uu = au[im][jn][2]; h1x = gg / (1.f + expf(-gg)) * uu;
                gg = ag[im][jn][3]; uu = au[im][jn][3]; h1y = gg / (1.f + expf(-gg)) * uu;
                *(__half2*)&g_H_h[b0i] = __floats2half2_rn(h0x, h0y);
                *(__half2*)&g_H_h[b1i] = __floats2half2_rn(h1x, h1y);
            }
        }
        CP_WAIT_0();
        __syncthreads();
    }
}

// GEMM2 (persistent) + fused combine: out[tok] += w * (H @ Wo^T)
__global__ __launch_bounds__(256, 2) void gemm2_kernel(float* __restrict__ out) {
    extern __shared__ __half sm[];
    __shared__ int   stok[BM];
    __shared__ float swt[BM];
    __shared__ int s_nb[NE];
    __shared__ int s_tile;
    int tid = threadIdx.x;
    if (tid < NE) s_nb[tid] = ((g_cnt[tid] + BM - 1) / BM) * G2_NT;
    __syncthreads();
    int tot = 0;
#pragma unroll
    for (int e = 0; e < NE; e++) tot += s_nb[e];

    uint32_t sb = su32(sm);
    int rr = tid >> 1;
    int ko = (tid & 1) * 16;
    uint32_t dstA = sb + (uint32_t)(rr * LDH + ko) * 2;
    uint32_t dstB = sb + G2_BOFF + (uint32_t)(rr * LDH + ko) * 2;

    int lane = tid & 31, wid = tid >> 5;
    int g = lane >> 2, t4 = lane & 3;
    int wm = wid & 3, wn = wid >> 2;

    uint32_t offA[2], offB[4];
#pragma unroll
    for (int im = 0; im < 2; im++)
        offA[im] = (uint32_t)((wm * 32 + im * 16 + (lane & 15)) * LDH + (lane >> 4) * 8) * 2;
#pragma unroll
    for (int p = 0; p < 4; p++)
        offB[p] = G2_BOFF + (uint32_t)((wn * 64 + (p * 2 + (lane >> 4)) * 8 + (lane & 7)) * LDH
                                       + ((lane >> 3) & 1) * 8) * 2;

    for (;;) {
        if (tid == 0) s_tile = atomicAdd(&g_work2, 1);
        __syncthreads();
        int t = s_tile;
        if (t >= tot) break;
        int e = 0, base = 0;
        while (t >= base + s_nb[e]) { base += s_nb[e]; e++; }
        int loc = t - base;
        int m0 = (loc / G2_NT) * BM;
        int n0 = (loc % G2_NT) * 128;
        int cnt = g_cnt[e];
        if (tid < BM) {
            int r = m0 + tid;
            bool v = r < cnt;
            stok[tid] = v ? g_tok[e * MAXR + r] : 0;
            swt[tid]  = v ? g_wrow[e * MAXR + r] : 0.f;
        }
        __syncthreads();

        const __half* srcA = g_H_h + (size_t)(e * MAXR + m0 + rr) * FF + ko;
        const __half* srcB = g_Wo_h + ((size_t)e * DIM + n0 + rr) * FF + ko;

#define G2_ISSUE(s, kt) do {                                           \
        uint32_t b_ = (uint32_t)(s) * G2_STAGE;                        \
        int kh_ = (kt) * BK;                                           \
        cp16(dstA + b_, srcA + kh_); cp16(dstA + b_ + 16, srcA + kh_ + 8); \
        cp16(dstB + b_, srcB + kh_); cp16(dstB + b_ + 16, srcB + kh_ + 8); \
    } while (0)

        float acc[2][8][4];
#pragma unroll
        for (int i = 0; i < 2; i++)
#pragma unroll
            for (int j = 0; j < 8; j++)
#pragma unroll
                for (int c = 0; c < 4; c++) acc[i][j][c] = 0.f;

        G2_ISSUE(0, 0); CP_COMMIT();
        G2_ISSUE(1, 1); CP_COMMIT();
        G2_ISSUE(2, 2); CP_COMMIT();

        const int NK = FF / BK;  // 96
        for (int kt = 0; kt < NK; kt++) {
            CP_WAIT_2();
            __syncthreads();
            if (kt + 3 < NK) G2_ISSUE((kt + 3) % NSTAGE, kt + 3);
            CP_COMMIT();
            uint32_t stb = sb + (uint32_t)(kt % NSTAGE) * G2_STAGE;
#pragma unroll
            for (int km = 0; km < 2; km++) {
                uint32_t kmo = km * 32;
                uint32_t a[2][4], bq[4][4];
                LDSM4(a[0], stb + offA[0] + kmo);
                LDSM4(a[1], stb + offA[1] + kmo);
#pragma unroll
                for (int p = 0; p < 4; p++) LDSM4(bq[p], stb + offB[p] + kmo);
#pragma unroll
                for (int p = 0; p < 4; p++) {
#pragma unroll
                    for (int s = 0; s < 2; s++) {
                        int jn = p * 2 + s;
#pragma unroll
                        for (int im = 0; im < 2; im++)
                            MMA_F16(acc[im][jn], a[im], bq[p][s * 2], bq[p][s * 2 + 1]);
                    }
                }
            }
        }

        // fused combine epilogue: out[tok, col] += w * acc  (<=2 commutative contributions
        // per element -> order-independent -> deterministic)
#pragma unroll
        for (int im = 0; im < 2; im++) {
            int rl0 = wm * 32 + im * 16 + g;
            int rl1 = rl0 + 8;
            int tok0 = stok[rl0]; float w0 = swt[rl0];
            int tok1 = stok[rl1]; float w1 = swt[rl1];
            float* o0 = out + (size_t)tok0 * DIM;
            float* o1 = out + (size_t)tok1 * DIM;
#pragma unroll
            for (int jn = 0; jn < 8; jn++) {
                int col = n0 + wn * 64 + jn * 8 + t4 * 2;
                if (w0 > 0.f) {
                    atomicAdd(o0 + col,     w0 * acc[im][jn][0]);
                    atomicAdd(o0 + col + 1, w0 * acc[im][jn][1]);
                }
                if (w1 > 0.f) {
                    atomicAdd(o1 + col,     w1 * acc[im][jn][2]);
                    atomicAdd(o1 + col + 1, w1 * acc[im][jn][3]);
                }
            }
        }
        CP_WAIT_0();
        __syncthreads();
    }
}

// ---------------- finalize ----------------
__global__ void finalize_kernel(float* __restrict__ out, int out_size) {
    if (threadIdx.x == 0 && out_size > T_TOK * DIM) {
        float lb = 0.f;
        for (int e = 0; e < NE; e++) {
            float f = (float)g_cnta[e] / (float)(T_TOK * 2);
            float P = g_psum[e] / (float)T_TOK;
            lb += f * P;
        }
        lb *= (float)NE;
        float z = g_zsum / (float)T_TOK;
        out[T_TOK * DIM] = 0.01f * lb + 0.001f * z;
    }
}

// ---------------- launch ----------------
extern "C" void kernel_launch(void* const* d_in, const int* in_sizes, int n_in,
                              void* d_out, int out_size) {
    (void)in_sizes; (void)n_in;
    const float* x   = (const float*)d_in[0];
    const float* wg  = (const float*)d_in[1];
    const float* wig = (const float*)d_in[2];
    const float* wiu = (const float*)d_in[3];
    const float* wo  = (const float*)d_in[4];
    float* out = (float*)d_out;

    const int G1_SMEM = NSTAGE * G1_STAGE;  // 81920 bytes
    const int G2_SMEM = NSTAGE * G2_STAGE;  // 81920 bytes
    cudaFuncSetAttribute(gemm1_kernel, cudaFuncAttributeMaxDynamicSharedMemorySize, G1_SMEM);
    cudaFuncSetAttribute(gemm2_kernel, cudaFuncAttributeMaxDynamicSharedMemorySize, G2_SMEM);

    prep_kernel<<<(PREP_THREADS + 255) / 256, 256>>>(x, wig, wiu, wo, out);
    router_kernel<<<T_TOK / 16, 512>>>(x, wg);
    scan_kernel<<<NE, 1024>>>();
    gemm1_kernel<<<PERSIST_CTAS, 256, G1_SMEM>>>();
    gemm2_kernel<<<PERSIST_CTAS, 256, G2_SMEM>>>(out);
    finalize_kernel<<<1, 1>>>(out, out_size);
}

// round 16
// speedup vs baseline: 1.0347x; 1.0035x over previous
#include <cuda_runtime.h>
#include <cuda_fp16.h>
#include <math.h>
#include <stdint.h>

#define T_TOK 8192
#define DIM   768
#define FF    3072
#define NE    8
#define CAP   2560
#define MAXR  5120   // 2*CAP, max gathered rows per expert
#define MAXMB 40     // max 128-row blocks per expert (MAXR/128)

// ---------------- static device scratch ----------------
__device__ __half g_Wg_h[(size_t)NE * FF * DIM];
__device__ __half g_Wu_h[(size_t)NE * FF * DIM];
__device__ __half g_Wo_h[(size_t)NE * DIM * FF];
__device__ __half g_X_h[(size_t)T_TOK * DIM];
__device__ __half g_H_h[(size_t)NE * MAXR * FF];
__device__ int    g_tok[NE * MAXR];
__device__ float  g_wrow[NE * MAXR];   // combine weight per gathered row
__device__ int    g_topk[T_TOK * 2];
__device__ float  g_topp[T_TOK * 2];
__device__ int    g_cnt[NE];
__device__ int    g_work;              // merged persistent-GEMM tile counter
__device__ int    g_done[NE * MAXMB];  // gemm1 n-tile completion counters

#define ROUTER_BLOCKS (T_TOK / 8)      // 1024 router blocks, 8 tokens each
__device__ float  g_psum_part[ROUTER_BLOCKS * NE];
__device__ int    g_cnta_part[ROUTER_BLOCKS * NE];
__device__ float  g_zsum_part[ROUTER_BLOCKS];

// ---------------- helpers ----------------
__device__ __forceinline__ uint32_t su32(const void* p) {
    uint32_t a;
    asm("{ .reg .u64 t; cvta.to.shared.u64 t, %1; cvt.u32.u64 %0, t; }" : "=r"(a) : "l"(p));
    return a;
}
__device__ __forceinline__ void cp16(uint32_t dst, const void* src) {
    asm volatile("cp.async.cg.shared.global [%0], [%1], 16;" :: "r"(dst), "l"(src) : "memory");
}
#define CP_COMMIT() asm volatile("cp.async.commit_group;" ::: "memory")
#define CP_WAIT_2() asm volatile("cp.async.wait_group 2;" ::: "memory")
#define CP_WAIT_0() asm volatile("cp.async.wait_group 0;" ::: "memory")

#define MMA_F16(D, A, B0, B1)                                                    \
    asm volatile(                                                                \
        "mma.sync.aligned.m16n8k16.row.col.f32.f16.f16.f32 "                     \
        "{%0,%1,%2,%3}, {%4,%5,%6,%7}, {%8,%9}, {%0,%1,%2,%3};\n"                \
        : "+f"((D)[0]), "+f"((D)[1]), "+f"((D)[2]), "+f"((D)[3])                 \
        : "r"((A)[0]), "r"((A)[1]), "r"((A)[2]), "r"((A)[3]), "r"(B0), "r"(B1))

#define LDSM4(R, addr)                                                           \
    asm volatile("ldmatrix.sync.aligned.m8n8.x4.shared.b16 {%0,%1,%2,%3}, [%4];" \
        : "=r"((R)[0]), "=r"((R)[1]), "=r"((R)[2]), "=r"((R)[3]) : "r"(addr))

// ---------------- fused prep: router + out-zero + fp32->fp16 cvt + counter init ----------------
#define NX8 ((T_TOK * DIM) / 8)          // 786432 packs (16B fp16 each)
#define NW8 ((NE * FF * DIM) / 8)        // 2359296
#define CVT_TOT (NX8 + 3 * NW8)          // 7864320 packs
#define CVT_HALF (CVT_TOT / 2)           // 3932160 threads, 2 packs each
#define ZERO_THREADS ((T_TOK * DIM) / 8) // 786432 threads, 2 float4 each
#define WORK_THREADS (CVT_HALF + ZERO_THREADS)
#define WORK_BLOCKS  ((WORK_THREADS + 255) / 256)

__device__ __forceinline__ uint4 cvt_pack(float4 v0, float4 v1) {
    __half2 h0 = __floats2half2_rn(v0.x, v0.y);
    __half2 h1 = __floats2half2_rn(v0.z, v0.w);
    __half2 h2 = __floats2half2_rn(v1.x, v1.y);
    __half2 h3 = __floats2half2_rn(v1.z, v1.w);
    uint4 o;
    o.x = *(const uint32_t*)&h0; o.y = *(const uint32_t*)&h1;
    o.z = *(const uint32_t*)&h2; o.w = *(const uint32_t*)&h3;
    return o;
}

__global__ void prep_kernel(const float* __restrict__ x,  const float* __restrict__ wig,
                            const float* __restrict__ wiu, const float* __restrict__ wo,
                            const float* __restrict__ wg,  float* __restrict__ out) {
    __shared__ float shp[NE];
    __shared__ int   shc[NE];
    __shared__ float shz;
    int tid = threadIdx.x;

    if (blockIdx.x < ROUTER_BLOCKS) {
        // ---- router branch: 8 tokens per block (1 warp/token); NO smem gate (stream from L2) ----
        int blk = blockIdx.x;
        if (tid < NE) { shp[tid] = 0.f; shc[tid] = 0; }
        if (tid == 0) shz = 0.f;
        __syncthreads();

        int w = tid >> 5, lane = tid & 31;
        int t = blk * 8 + w;
        const float* xt = x + (size_t)t * DIM;
        float acc[NE];
#pragma unroll
        for (int e = 0; e < NE; e++) acc[e] = 0.f;
        for (int j = lane; j < DIM; j += 32) {
            float xv = xt[j];
#pragma unroll
            for (int e = 0; e < NE; e++) acc[e] += xv * __ldg(&wg[e * DIM + j]);
        }
#pragma unroll
        for (int o = 16; o > 0; o >>= 1) {
#pragma unroll
            for (int e = 0; e < NE; e++) acc[e] += __shfl_xor_sync(0xffffffffu, acc[e], o);
        }
        if (lane == 0) {
            float m = acc[0];
#pragma unroll
            for (int e = 1; e < NE; e++) m = fmaxf(m, acc[e]);
            float p[NE]; float s = 0.f;
#pragma unroll
            for (int e = 0; e < NE; e++) { p[e] = expf(acc[e] - m); s += p[e]; }
            float inv = 1.f / s;
#pragma unroll
            for (int e = 0; e < NE; e++) p[e] *= inv;
            float lse = m + logf(s);
            int i0 = 0; float b0 = p[0];
#pragma unroll
            for (int e = 1; e < NE; e++) if (p[e] > b0) { b0 = p[e]; i0 = e; }
            int i1 = -1; float b1 = -1.f;
#pragma unroll
            for (int e = 0; e < NE; e++) if (e != i0 && p[e] > b1) { b1 = p[e]; i1 = e; }
            float invs = 1.f / (b0 + b1);
            g_topk[t * 2] = i0; g_topk[t * 2 + 1] = i1;
            g_topp[t * 2] = b0 * invs; g_topp[t * 2 + 1] = b1 * invs;
#pragma unroll
            for (int e = 0; e < NE; e++) atomicAdd(&shp[e], p[e]);
            atomicAdd(&shc[i0], 1);
            atomicAdd(&shc[i1], 1);
            atomicAdd(&shz, lse * lse);
        }
        __syncthreads();
        if (tid < NE) {
            g_psum_part[blk * NE + tid] = shp[tid];
            g_cnta_part[blk * NE + tid] = shc[tid];
        }
        if (tid == 0) g_zsum_part[blk] = shz;
        return;
    }

    // ---- cvt / zero / counter-init branch ----
    int i = (blockIdx.x - ROUTER_BLOCKS) * 256 + tid;
    if (i < CVT_HALF) {
        int j = 2 * i;
        const float* s;
        __half* d;
        int k;
        if (j < NX8)                { s = x;   d = g_X_h;  k = j; }
        else if (j < NX8 + NW8)     { s = wig; d = g_Wg_h; k = j - NX8; }
        else if (j < NX8 + 2 * NW8) { s = wiu; d = g_Wu_h; k = j - NX8 - NW8; }
        else                        { s = wo;  d = g_Wo_h; k = j - NX8 - 2 * NW8; }
        float4 v0 = ((const float4*)s)[2 * k];
        float4 v1 = ((const float4*)s)[2 * k + 1];
        float4 v2 = ((const float4*)s)[2 * k + 2];
        float4 v3 = ((const float4*)s)[2 * k + 3];
        ((uint4*)d)[k]     = cvt_pack(v0, v1);
        ((uint4*)d)[k + 1] = cvt_pack(v2, v3);
    } else if (i < WORK_THREADS) {
        int z = i - CVT_HALF;
        float4 zz = make_float4(0.f, 0.f, 0.f, 0.f);
        ((float4*)out)[2 * z]     = zz;
        ((float4*)out)[2 * z + 1] = zz;
        if (z == 0) g_work = 0;
        if (z >= 1 && z <= NE * MAXMB) g_done[z - 1] = 0;
    }
}

// ---------------- scan: 1024 threads, 8 stripes ----------------
__global__ void scan_kernel() {
    int e = blockIdx.x;
    int tid = threadIdx.x;
    int w = tid >> 5, lane = tid & 31;
    unsigned ltm = (1u << lane) - 1u;
    __shared__ int sw0[32], sw1[32], sws[32];
    __shared__ int base0, base1, baseS;
    if (tid == 0) { base0 = 0; base1 = 0; baseS = 0; }
    __syncthreads();
    for (int b = 0; b < T_TOK; b += 1024) {
        int t = b + tid;
        int i0 = g_topk[t * 2], i1 = g_topk[t * 2 + 1];
        int a0 = (i0 == e) ? 1 : 0;
        int a1 = (i1 == e) ? 1 : 0;
        unsigned m0b = __ballot_sync(0xffffffffu, a0);
        unsigned m1b = __ballot_sync(0xffffffffu, a1);
        if (lane == 0) { sw0[w] = __popc(m0b); sw1[w] = __popc(m1b); }
        __syncthreads();
        int off0 = base0, off1 = base1;
        for (int j = 0; j < w; j++) { off0 += sw0[j]; off1 += sw1[j]; }
        int r0 = off0 + __popc(m0b & ltm);
        int r1 = off1 + __popc(m1b & ltm);
        int k0 = a0 && (r0 < CAP);
        int k1 = a1 && (r1 < CAP);
        int sel = (k0 || k1) ? 1 : 0;
        unsigned msb = __ballot_sync(0xffffffffu, sel);
        if (lane == 0) sws[w] = __popc(msb);
        __syncthreads();
        int offS = baseS;
        for (int j = 0; j < w; j++) offS += sws[j];
        int pos = offS + __popc(msb & ltm);
        if (sel) {
            g_tok[e * MAXR + pos] = t;
            g_wrow[e * MAXR + pos] = k0 ? g_topp[t * 2] : g_topp[t * 2 + 1];
        }
        __syncthreads();
        if (tid == 0) {
            int t0 = 0, t1 = 0, ts = 0;
            for (int j = 0; j < 32; j++) { t0 += sw0[j]; t1 += sw1[j]; ts += sws[j]; }
            base0 += t0; base1 += t1; baseS += ts;
        }
        __syncthreads();
    }
    if (tid == 0) g_cnt[e] = baseS;
}

// ---------------- GEMM config (round-10 proven inner loops; merged persistent) ----------------
#define BM 128
#define BK 32
#define LDH 40
#define G1_STAGE 20480u
#define G1_GOFF  10240u
#define G1_UOFF  15360u
#define G2_STAGE 20480u
#define G2_BOFF  10240u
#define NSTAGE 4
#define G1_NT (FF / 64)        // 48
#define G2_NT (DIM / 128)      // 6
#define PERSIST_CTAS 304

// Merged persistent GEMM: queue = [all gemm1 tiles][all gemm2 tiles].
// gemm1 tile -> H; completion counted per (e, mblock). gemm2 tile spins on its counter.
__global__ __launch_bounds__(256, 2) void gemm_kernel(float* __restrict__ out) {
    extern __shared__ __half sm[];
    __shared__ int   stok[BM];
    __shared__ float swt[BM];
    __shared__ int   s_mb[NE];
    __shared__ int   s_tile;
    int tid = threadIdx.x;
    if (tid < NE) s_mb[tid] = (g_cnt[tid] + BM - 1) / BM;
    __syncthreads();
    int tot1 = 0, tot2 = 0;
#pragma unroll
    for (int e = 0; e < NE; e++) { tot1 += s_mb[e] * G1_NT; tot2 += s_mb[e] * G2_NT; }
    int tot = tot1 + tot2;

    uint32_t sb = su32(sm);
    int rr = tid >> 1;
    int ko = (tid & 1) * 16;
    uint32_t dstA  = sb + (uint32_t)(rr * LDH + ko) * 2;
    int bro = (tid & 127) >> 1;
    uint32_t dstB1 = sb + ((tid < 128) ? G1_GOFF : G1_UOFF) + (uint32_t)(bro * LDH + ko) * 2;
    uint32_t dstB2 = sb + G2_BOFF + (uint32_t)(rr * LDH + ko) * 2;

    int lane = tid & 31, wid = tid >> 5;
    int g = lane >> 2, t4 = lane & 3;
    int wm = wid & 3, wn = wid >> 2;

    uint32_t offA[2], offB1[2], offB2[4];
#pragma unroll
    for (int im = 0; im < 2; im++)
        offA[im] = (uint32_t)((wm * 32 + im * 16 + (lane & 15)) * LDH + (lane >> 4) * 8) * 2;
#pragma unroll
    for (int p = 0; p < 2; p++)
        offB1[p] = G1_GOFF + (uint32_t)((wn * 32 + (p * 2 + (lane >> 4)) * 8 + (lane & 7)) * LDH
                                        + ((lane >> 3) & 1) * 8) * 2;
#pragma unroll
    for (int p = 0; p < 4; p++)
        offB2[p] = G2_BOFF + (uint32_t)((wn * 64 + (p * 2 + (lane >> 4)) * 8 + (lane & 7)) * LDH
                                        + ((lane >> 3) & 1) * 8) * 2;

    for (;;) {
        if (tid == 0) s_tile = atomicAdd(&g_work, 1);
        __syncthreads();
        int t = s_tile;
        if (t >= tot) break;

        if (t < tot1) {
            // ================= GEMM1 tile =================
            int e = 0, base = 0;
            while (t >= base + s_mb[e] * G1_NT) { base += s_mb[e] * G1_NT; e++; }
            int loc = t - base;
            int mb = loc / G1_NT;
            int m0 = mb * BM;
            int n0 = (loc % G1_NT) * 64;
            int cnt = g_cnt[e];
            if (tid < BM) { int r = m0 + tid; stok[tid] = (r < cnt) ? g_tok[e * MAXR + r] : 0; }
            __syncthreads();

            const __half* srcA = g_X_h + (size_t)stok[rr] * DIM + ko;
            const __half* srcB = ((tid < 128) ? g_Wg_h : g_Wu_h)
                                 + ((size_t)e * FF + n0 + bro) * DIM + ko;

#define G1_ISSUE(s, kt) do {                                              \
            uint32_t b_ = (uint32_t)(s) * G1_STAGE;                       \
            int kh_ = (kt) * BK;                                          \
            cp16(dstA + b_, srcA + kh_); cp16(dstA + b_ + 16, srcA + kh_ + 8); \
            cp16(dstB1 + b_, srcB + kh_); cp16(dstB1 + b_ + 16, srcB + kh_ + 8); \
        } while (0)

            float ag[2][4][4], au[2][4][4];
#pragma unroll
            for (int i = 0; i < 2; i++)
#pragma unroll
                for (int j = 0; j < 4; j++)
#pragma unroll
                    for (int c = 0; c < 4; c++) { ag[i][j][c] = 0.f; au[i][j][c] = 0.f; }

            G1_ISSUE(0, 0); CP_COMMIT();
            G1_ISSUE(1, 1); CP_COMMIT();
            G1_ISSUE(2, 2); CP_COMMIT();

            const int NK = DIM / BK;  // 24
            for (int kt = 0; kt < NK; kt++) {
                CP_WAIT_2();
                __syncthreads();
                if (kt + 3 < NK) G1_ISSUE((kt + 3) % NSTAGE, kt + 3);
                CP_COMMIT();
                uint32_t stb = sb + (uint32_t)(kt % NSTAGE) * G1_STAGE;
#pragma unroll
                for (int km = 0; km < 2; km++) {
                    uint32_t kmo = km * 32;
                    uint32_t a[2][4], gq[2][4], uq[2][4];
                    LDSM4(a[0], stb + offA[0] + kmo);
                    LDSM4(a[1], stb + offA[1] + kmo);
                    LDSM4(gq[0], stb + offB1[0] + kmo);
                    LDSM4(gq[1], stb + offB1[1] + kmo);
                    LDSM4(uq[0], stb + offB1[0] + (G1_UOFF - G1_GOFF) + kmo);
                    LDSM4(uq[1], stb + offB1[1] + (G1_UOFF - G1_GOFF) + kmo);
#pragma unroll
                    for (int p = 0; p < 2; p++) {
#pragma unroll
                        for (int s = 0; s < 2; s++) {
                            int jn = p * 2 + s;
#pragma unroll
                            for (int im = 0; im < 2; im++) {
                                MMA_F16(ag[im][jn], a[im], gq[p][s * 2], gq[p][s * 2 + 1]);
                                MMA_F16(au[im][jn], a[im], uq[p][s * 2], uq[p][s * 2 + 1]);
                            }
                        }
                    }
                }
            }

            // epilogue: h = silu(g) * u -> fp16 H
#pragma unroll
            for (int im = 0; im < 2; im++) {
#pragma unroll
                for (int jn = 0; jn < 4; jn++) {
                    int rl  = wm * 32 + im * 16 + g;
                    int col = n0 + wn * 32 + jn * 8 + t4 * 2;
                    size_t b0i = (size_t)(e * MAXR + m0 + rl) * FF + col;
                    size_t b1i = (size_t)(e * MAXR + m0 + rl + 8) * FF + col;
                    float gg, uu, h0x, h0y, h1x, h1y;
                    gg = ag[im][jn][0]; uu = au[im][jn][0]; h0x = gg / (1.f + expf(-gg)) * uu;
                    gg = ag[im][jn][1]; uu = au[im][jn][1]; h0y = gg / (1.f + expf(-gg)) * uu;
                    gg = ag[im][jn][2]; uu = au[im][jn][2]; h1x = gg / (1.f + expf(-gg)) * uu;
                    gg = ag[im][jn][3]; uu = au[im][jn][3]; h1y = gg / (1.f + expf(-gg)) * uu;
                    *(__half2*)&g_H_h[b0i] = __floats2half2_rn(h0x, h0y);
                    *(__half2*)&g_H_h[b1i] = __floats2half2_rn(h1x, h1y);
                }
            }
            CP_WAIT_0();
            __threadfence();           // make H visible before signaling
            __syncthreads();           // all threads' stores done
            if (tid == 0) atomicAdd(&g_done[e * MAXMB + mb], 1);
        } else {
            // ================= GEMM2 tile (+ fused combine) =================
            int t2 = t - tot1;
            int e = 0, base = 0;
            while (t2 >= base + s_mb[e] * G2_NT) { base += s_mb[e] * G2_NT; e++; }
            int loc = t2 - base;
            int mb = loc / G2_NT;
            int m0 = mb * BM;
            int n0 = (loc % G2_NT) * 128;
            int cnt = g_cnt[e];
            if (tid < BM) {
                int r = m0 + tid;
                bool v = r < cnt;
                stok[tid] = v ? g_tok[e * MAXR + r] : 0;
                swt[tid]  = v ? g_wrow[e * MAXR + r] : 0.f;
            }
            // dependency: all 48 gemm1 n-tiles of (e, mb) complete
            if (tid == 0) {
                while (((volatile int*)g_done)[e * MAXMB + mb] < G1_NT) __nanosleep(64);
            }
            __syncthreads();
            __threadfence();

            const __half* srcA = g_H_h + (size_t)(e * MAXR + m0 + rr) * FF + ko;
            const __half* srcB = g_Wo_h + ((size_t)e * DIM + n0 + rr) * FF + ko;

#define G2_ISSUE(s, kt) do {                                              \
            uint32_t b_ = (uint32_t)(s) * G2_STAGE;                       \
            int kh_ = (kt) * BK;                                          \
            cp16(dstA + b_, srcA + kh_); cp16(dstA + b_ + 16, srcA + kh_ + 8); \
            cp16(dstB2 + b_, srcB + kh_); cp16(dstB2 + b_ + 16, srcB + kh_ + 8); \
        } while (0)

            float acc[2][8][4];
#pragma unroll
            for (int i = 0; i < 2; i++)
#pragma unroll
                for (int j = 0; j < 8; j++)
#pragma unroll
                    for (int c = 0; c < 4; c++) acc[i][j][c] = 0.f;

            G2_ISSUE(0, 0); CP_COMMIT();
            G2_ISSUE(1, 1); CP_COMMIT();
            G2_ISSUE(2, 2); CP_COMMIT();

            const int NK = FF / BK;  // 96
            for (int kt = 0; kt < NK; kt++) {
                CP_WAIT_2();
                __syncthreads();
                if (kt + 3 < NK) G2_ISSUE((kt + 3) % NSTAGE, kt + 3);
                CP_COMMIT();
                uint32_t stb = sb + (uint32_t)(kt % NSTAGE) * G2_STAGE;
#pragma unroll
                for (int km = 0; km < 2; km++) {
                    uint32_t kmo = km * 32;
                    uint32_t a[2][4], bq[4][4];
                    LDSM4(a[0], stb + offA[0] + kmo);
                    LDSM4(a[1], stb + offA[1] + kmo);
#pragma unroll
                    for (int p = 0; p < 4; p++) LDSM4(bq[p], stb + offB2[p] + kmo);
#pragma unroll
                    for (int p = 0; p < 4; p++) {
#pragma unroll
                        for (int s = 0; s < 2; s++) {
                            int jn = p * 2 + s;
#pragma unroll
                            for (int im = 0; im < 2; im++)
                                MMA_F16(acc[im][jn], a[im], bq[p][s * 2], bq[p][s * 2 + 1]);
                        }
                    }
                }
            }

            // fused combine: out[tok, col] += w * acc (<=2 commutative adds per element)
#pragma unroll
            for (int im = 0; im < 2; im++) {
                int rl0 = wm * 32 + im * 16 + g;
                int rl1 = rl0 + 8;
                int tok0 = stok[rl0]; float w0 = swt[rl0];
                int tok1 = stok[rl1]; float w1 = swt[rl1];
                float* o0 = out + (size_t)tok0 * DIM;
                float* o1 = out + (size_t)tok1 * DIM;
#pragma unroll
                for (int jn = 0; jn < 8; jn++) {
                    int col = n0 + wn * 64 + jn * 8 + t4 * 2;
                    if (w0 > 0.f) {
                        atomicAdd(o0 + col,     w0 * acc[im][jn][0]);
                        atomicAdd(o0 + col + 1, w0 * acc[im][jn][1]);
                    }
                    if (w1 > 0.f) {
                        atomicAdd(o1 + col,     w1 * acc[im][jn][2]);
                        atomicAdd(o1 + col + 1, w1 * acc[im][jn][3]);
                    }
                }
            }
            CP_WAIT_0();
            __syncthreads();
        }
    }
}

// ---------------- finalize: parallel reduction of router partials + aux loss ----------------
__global__ void finalize_kernel(float* __restrict__ out, int out_size) {
    if (out_size <= T_TOK * DIM) return;
    __shared__ float wp[32][NE];
    __shared__ int   wc[32][NE];
    __shared__ float wz[32];
    int tid = threadIdx.x;        // 1024 threads; one per router block
    int lane = tid & 31, w = tid >> 5;

    float p[NE]; int c[NE];
#pragma unroll
    for (int e = 0; e < NE; e++) {
        p[e] = g_psum_part[tid * NE + e];
        c[e] = g_cnta_part[tid * NE + e];
    }
    float z = g_zsum_part[tid];
#pragma unroll
    for (int o = 16; o > 0; o >>= 1) {
#pragma unroll
        for (int e = 0; e < NE; e++) {
            p[e] += __shfl_xor_sync(0xffffffffu, p[e], o);
            c[e] += __shfl_xor_sync(0xffffffffu, c[e], o);
        }
        z += __shfl_xor_sync(0xffffffffu, z, o);
    }
    if (lane == 0) {
#pragma unroll
        for (int e = 0; e < NE; e++) { wp[w][e] = p[e]; wc[w][e] = c[e]; }
        wz[w] = z;
    }
    __syncthreads();
    if (w == 0) {
#pragma unroll
        for (int e = 0; e < NE; e++) { p[e] = wp[lane][e]; c[e] = wc[lane][e]; }
        z = wz[lane];
#pragma unroll
        for (int o = 16; o > 0; o >>= 1) {
#pragma unroll
            for (int e = 0; e < NE; e++) {
                p[e] += __shfl_xor_sync(0xffffffffu, p[e], o);
                c[e] += __shfl_xor_sync(0xffffffffu, c[e], o);
            }
            z += __shfl_xor_sync(0xffffffffu, z, o);
        }
        if (lane == 0) {
            float lb = 0.f;
#pragma unroll
            for (int e = 0; e < NE; e++) {
                float f = (float)c[e] / (float)(T_TOK * 2);
                float P = p[e] / (float)T_TOK;
                lb += f * P;
            }
            lb *= (float)NE;
            out[T_TOK * DIM] = 0.01f * lb + 0.001f * (z / (float)T_TOK);
        }
    }
}

// ---------------- launch ----------------
extern "C" void kernel_launch(void* const* d_in, const int* in_sizes, int n_in,
                              void* d_out, int out_size) {
    (void)in_sizes; (void)n_in;
    const float* x   = (const float*)d_in[0];
    const float* wg  = (const float*)d_in[1];
    const float* wig = (const float*)d_in[2];
    const float* wiu = (const float*)d_in[3];
    const float* wo  = (const float*)d_in[4];
    float* out = (float*)d_out;

    const int G_SMEM = NSTAGE * G1_STAGE;  // 81920 bytes
    cudaFuncSetAttribute(gemm_kernel, cudaFuncAttributeMaxDynamicSharedMemorySize, G_SMEM);

    prep_kernel<<<ROUTER_BLOCKS + WORK_BLOCKS, 256>>>(x, wig, wiu, wo, wg, out);
    scan_kernel<<<NE, 1024>>>();
    gemm_kernel<<<PERSIST_CTAS, 256, G_SMEM>>>(out);
    finalize_kernel<<<1, 1024>>>(out, out_size);
}